// round 6
// baseline (speedup 1.0000x reference)
#include <cuda_runtime.h>
#include <cuda_fp16.h>
#include <math.h>
#include <stdint.h>

#define BATCH 4
#define SEQ   2048
#define DIM   1024
#define NHEAD 16
#define DH    64
#define NROWS (BATCH*SEQ)   // 8192

// ---------------- scratch (device globals) ----------------
// hi/lo fp16 planes
__device__ __half g_Xh[(size_t)NROWS * DIM];
__device__ __half g_Xl[(size_t)NROWS * DIM];
__device__ __half g_Wh[(size_t)4 * DIM * DIM];
__device__ __half g_Wl[(size_t)4 * DIM * DIM];
__device__ __half g_Qh[(size_t)NROWS * DIM];
__device__ __half g_Ql[(size_t)NROWS * DIM];
__device__ __half g_Kh[(size_t)NROWS * DIM];
__device__ __half g_Kl[(size_t)NROWS * DIM];
__device__ __half g_Vh[(size_t)NROWS * DIM];
__device__ __half g_Vl[(size_t)NROWS * DIM];
__device__ __half g_Oh[(size_t)NROWS * DIM];
__device__ __half g_Ol[(size_t)NROWS * DIM];
__device__ float g_cos[SEQ * 32];
__device__ float g_sin[SEQ * 32];

// ---------------- helpers ----------------
__device__ __forceinline__ void splitf(float x, __half& h, __half& l) {
    h = __float2half_rn(x);
    l = __float2half_rn(x - __half2float(h));
}
__device__ __forceinline__ void mma16(float* c, const uint32_t* a, const uint32_t* b) {
    asm volatile(
        "mma.sync.aligned.m16n8k16.row.col.f32.f16.f16.f32 "
        "{%0,%1,%2,%3},{%4,%5,%6,%7},{%8,%9},{%0,%1,%2,%3};"
        : "+f"(c[0]), "+f"(c[1]), "+f"(c[2]), "+f"(c[3])
        : "r"(a[0]), "r"(a[1]), "r"(a[2]), "r"(a[3]), "r"(b[0]), "r"(b[1]));
}
__device__ __forceinline__ void ldmx4t(uint32_t& d0, uint32_t& d1, uint32_t& d2, uint32_t& d3,
                                       uint32_t saddr) {
    asm volatile("ldmatrix.sync.aligned.m8n8.x4.trans.shared.b16 {%0,%1,%2,%3}, [%4];"
                 : "=r"(d0), "=r"(d1), "=r"(d2), "=r"(d3) : "r"(saddr));
}
__device__ __forceinline__ void cp16h(__half* dst, const __half* src) {
    unsigned s = (unsigned)__cvta_generic_to_shared(dst);
    asm volatile("cp.async.ca.shared.global [%0], [%1], 16;" :: "r"(s), "l"(src));
}
__device__ __forceinline__ void cp_commit() { asm volatile("cp.async.commit_group;"); }
template<int N>
__device__ __forceinline__ void cp_wait() { asm volatile("cp.async.wait_group %0;" :: "n"(N)); }

// ---------------- RoPE table ----------------
__global__ void rope_table_kernel(const int* __restrict__ pos)
{
    int idx = blockIdx.x * blockDim.x + threadIdx.x;
    if (idx >= SEQ * 32) return;
    int s = idx >> 5;
    int p = idx & 31;
    float inv = powf(10000.0f, -(float)(2 * p) / (float)DH);
    float ang = (float)pos[s] * inv;
    float sv, cv;
    sincosf(ang, &sv, &cv);
    g_cos[idx] = cv;
    g_sin[idx] = sv;
}

// ---------------- converters: fp32 -> hi/lo fp16 planes ----------------
__global__ void convert_x_kernel(const float* __restrict__ x)
{
    size_t i = ((size_t)blockIdx.x * blockDim.x + threadIdx.x) * 4;
    if (i >= (size_t)NROWS * DIM) return;
    float4 v = *(const float4*)(x + i);
    __half h0, l0, h1, l1, h2, l2, h3, l3;
    splitf(v.x, h0, l0); splitf(v.y, h1, l1);
    splitf(v.z, h2, l2); splitf(v.w, h3, l3);
    *(__half2*)&g_Xh[i]     = __halves2half2(h0, h1);
    *(__half2*)&g_Xh[i + 2] = __halves2half2(h2, h3);
    *(__half2*)&g_Xl[i]     = __halves2half2(l0, l1);
    *(__half2*)&g_Xl[i + 2] = __halves2half2(l2, l3);
}
__global__ void convert_w_kernel(const float* __restrict__ W, int widx)
{
    size_t i = ((size_t)blockIdx.x * blockDim.x + threadIdx.x) * 4;
    if (i >= (size_t)DIM * DIM) return;
    size_t o = (size_t)widx * DIM * DIM + i;
    float4 v = *(const float4*)(W + i);
    v.x *= 256.0f; v.y *= 256.0f; v.z *= 256.0f; v.w *= 256.0f;
    __half h0, l0, h1, l1, h2, l2, h3, l3;
    splitf(v.x, h0, l0); splitf(v.y, h1, l1);
    splitf(v.z, h2, l2); splitf(v.w, h3, l3);
    *(__half2*)&g_Wh[o]     = __halves2half2(h0, h1);
    *(__half2*)&g_Wh[o + 2] = __halves2half2(h2, h3);
    *(__half2*)&g_Wl[o]     = __halves2half2(l0, l1);
    *(__half2*)&g_Wl[o + 2] = __halves2half2(l2, l3);
}

// ---------------- fp16x2 tensor-core GEMM, cp.async double-buffered ----------------
// C[i,j] = sum_d X[i,d] * W[j,d]; CTA 128x128, chunk K=32.
// MODE: 0 -> Qh/Ql (RoPE), 1 -> Kh/Kl (RoPE), 2 -> Vh/Vl, 3 -> A=Oh/Ol, C=Cout fp32
#define GKP 40                    // halves per row (80B, 16B-aligned)
#define GPL (128 * GKP)           // 5120 halves per plane
#define GSTG (4 * GPL)            // halves per stage
#define GEMM_SMEM (2 * GSTG * 2)  // 81920 B

template<int MODE>
__global__ void __launch_bounds__(256, 2) gemm_h2(float* __restrict__ Cout)
{
    extern __shared__ __half smh[];
    const __half* Aph = (MODE == 3) ? g_Oh : g_Xh;
    const __half* Apl = (MODE == 3) ? g_Ol : g_Xl;
    const __half* Bph = g_Wh + (size_t)MODE * DIM * DIM;
    const __half* Bpl = g_Wl + (size_t)MODE * DIM * DIM;

    const int tid  = threadIdx.x;
    const int lane = tid & 31;
    const int wid  = tid >> 5;
    const int g    = lane >> 2;
    const int t    = lane & 3;
    const int wm   = wid & 1;
    const int wn   = wid >> 1;

    const int row0 = blockIdx.y * 128;
    const int col0 = blockIdx.x * 128;

    float acc[4][4][4];
    #pragma unroll
    for (int im = 0; im < 4; im++)
        #pragma unroll
        for (int in = 0; in < 4; in++)
            #pragma unroll
            for (int e = 0; e < 4; e++)
                acc[im][in][e] = 0.0f;

    // stage loader: 4 planes x 128 rows x 4 (16B units) = 2048 units / 256 thr = 8 each
    auto load_stage = [&](int st, int kt) {
        const int k0 = kt * 32;
        #pragma unroll
        for (int i = 0; i < 8; i++) {
            int uidx = tid + i * 256;
            int p    = uidx >> 9;        // plane (uniform per warp)
            int w    = uidx & 511;
            int row  = w >> 2;
            int un   = (w & 3) * 8;      // half offset in row
            const __half* src;
            if (p == 0)      src = Aph + (size_t)(row0 + row) * DIM + k0 + un;
            else if (p == 1) src = Apl + (size_t)(row0 + row) * DIM + k0 + un;
            else if (p == 2) src = Bph + (size_t)(col0 + row) * DIM + k0 + un;
            else             src = Bpl + (size_t)(col0 + row) * DIM + k0 + un;
            cp16h(&smh[st * GSTG + p * GPL + row * GKP + un], src);
        }
    };

    load_stage(0, 0);
    cp_commit();

    const int NKT = DIM / 32;   // 32 chunks
    for (int kt = 0; kt < NKT; kt++) {
        const int st = kt & 1;
        cp_wait<0>();
        __syncthreads();
        if (kt + 1 < NKT) { load_stage(st ^ 1, kt + 1); cp_commit(); }

        const __half* Ah = smh + st * GSTG;
        const __half* Al = Ah + GPL;
        const __half* Bh = Ah + 2 * GPL;
        const __half* Bl = Ah + 3 * GPL;

        #pragma unroll
        for (int kq = 0; kq < 2; kq++) {
            const int kk = kq * 16;
            uint32_t bhi[4][2], blo[4][2];
            #pragma unroll
            for (int in = 0; in < 4; in++) {
                int col = wn * 32 + in * 8 + g;
                bhi[in][0] = *(const uint32_t*)&Bh[col * GKP + kk + 2 * t];
                bhi[in][1] = *(const uint32_t*)&Bh[col * GKP + kk + 8 + 2 * t];
                blo[in][0] = *(const uint32_t*)&Bl[col * GKP + kk + 2 * t];
                blo[in][1] = *(const uint32_t*)&Bl[col * GKP + kk + 8 + 2 * t];
            }
            #pragma unroll
            for (int im = 0; im < 4; im++) {
                int rb = wm * 64 + im * 16;
                uint32_t ahi[4], alo[4];
                ahi[0] = *(const uint32_t*)&Ah[(rb + g) * GKP + kk + 2 * t];
                ahi[1] = *(const uint32_t*)&Ah[(rb + 8 + g) * GKP + kk + 2 * t];
                ahi[2] = *(const uint32_t*)&Ah[(rb + g) * GKP + kk + 8 + 2 * t];
                ahi[3] = *(const uint32_t*)&Ah[(rb + 8 + g) * GKP + kk + 8 + 2 * t];
                alo[0] = *(const uint32_t*)&Al[(rb + g) * GKP + kk + 2 * t];
                alo[1] = *(const uint32_t*)&Al[(rb + 8 + g) * GKP + kk + 2 * t];
                alo[2] = *(const uint32_t*)&Al[(rb + g) * GKP + kk + 8 + 2 * t];
                alo[3] = *(const uint32_t*)&Al[(rb + 8 + g) * GKP + kk + 8 + 2 * t];
                #pragma unroll
                for (int in = 0; in < 4; in++) {
                    mma16(acc[im][in], ahi, bhi[in]);
                    mma16(acc[im][in], ahi, blo[in]);
                    mma16(acc[im][in], alo, bhi[in]);
                }
            }
        }
        __syncthreads();
    }

    // epilogue (undo W x256)
    const float sc = 1.0f / 256.0f;
    #pragma unroll
    for (int im = 0; im < 4; im++) {
        int r0 = row0 + wm * 64 + im * 16 + g;
        int r1 = r0 + 8;
        #pragma unroll
        for (int in = 0; in < 4; in++) {
            int c = col0 + wn * 32 + in * 8 + 2 * t;
            float v0 = acc[im][in][0] * sc, v1 = acc[im][in][1] * sc;
            float v2 = acc[im][in][2] * sc, v3 = acc[im][in][3] * sc;
            if (MODE == 3) {
                float2 o0 = { v0, v1 };
                float2 o1 = { v2, v3 };
                *(float2*)(Cout + (size_t)r0 * DIM + c) = o0;
                *(float2*)(Cout + (size_t)r1 * DIM + c) = o1;
            } else {
                if (MODE <= 1) {
                    int p = (c & 63) >> 1;
                    int s0 = r0 & (SEQ - 1);
                    int s1 = r1 & (SEQ - 1);
                    float cv0 = g_cos[s0 * 32 + p], sv0 = g_sin[s0 * 32 + p];
                    float cv1 = g_cos[s1 * 32 + p], sv1 = g_sin[s1 * 32 + p];
                    float n0 = v0 * cv0 - v1 * sv0, n1 = v0 * sv0 + v1 * cv0;
                    float n2 = v2 * cv1 - v3 * sv1, n3 = v2 * sv1 + v3 * cv1;
                    v0 = n0; v1 = n1; v2 = n2; v3 = n3;
                }
                __half* Ch = (MODE == 0) ? g_Qh : (MODE == 1) ? g_Kh : g_Vh;
                __half* Cl = (MODE == 0) ? g_Ql : (MODE == 1) ? g_Kl : g_Vl;
                __half h0, l0, h1, l1;
                splitf(v0, h0, l0); splitf(v1, h1, l1);
                *(__half2*)&Ch[(size_t)r0 * DIM + c] = __halves2half2(h0, h1);
                *(__half2*)&Cl[(size_t)r0 * DIM + c] = __halves2half2(l0, l1);
                splitf(v2, h0, l0); splitf(v3, h1, l1);
                *(__half2*)&Ch[(size_t)r1 * DIM + c] = __halves2half2(h0, h1);
                *(__half2*)&Cl[(size_t)r1 * DIM + c] = __halves2half2(l0, l1);
            }
        }
    }
}

// ---------------- flash attention, fp16x2 mma, pre-split inputs ----------------
#define AKP 72
#define OQH 0
#define OQL (128 * AKP)
#define OKH (2 * 128 * AKP)
#define OKL (OKH + 64 * AKP)
#define OVH (OKH + 2 * 64 * AKP)
#define OVL (OVH + 64 * AKP)
#define OPH (OVH + 2 * 64 * AKP)
#define OPL (OPH + 128 * AKP)
#define ATT_SMEM ((OPL + 128 * AKP) * 2)   // 110592 B

__global__ void __launch_bounds__(128) attn_h2_kernel()
{
    extern __shared__ __half smh[];
    __half* qh = smh + OQH;  __half* ql = smh + OQL;
    __half* kh = smh + OKH;  __half* kl = smh + OKL;
    __half* vh = smh + OVH;  __half* vl = smh + OVL;
    __half* ph = smh + OPH;  __half* pl = smh + OPL;
    const uint32_t sb = (uint32_t)__cvta_generic_to_shared(smh);

    const int tid  = threadIdx.x;
    const int lane = tid & 31;
    const int wid  = tid >> 5;
    const int g    = lane >> 2;
    const int t    = lane & 3;

    const int qt = blockIdx.x;
    const int q0 = qt * 128;
    const int bh = blockIdx.y;
    const int b  = bh >> 4;
    const int h  = bh & 15;

    const size_t base = (size_t)b * SEQ * DIM + h * DH;
    const __half* Qhb = g_Qh + base;  const __half* Qlb = g_Ql + base;
    const __half* Khb = g_Kh + base;  const __half* Klb = g_Kl + base;
    const __half* Vhb = g_Vh + base;  const __half* Vlb = g_Vl + base;

    // load Q planes (128 x 64 halves each)
    #pragma unroll
    for (int i = 0; i < 8; i++) {
        int pos = tid + i * 128;
        int row = pos >> 3;
        int u   = (pos & 7) * 8;
        *(uint4*)&qh[row * AKP + u] = *(const uint4*)(Qhb + (size_t)(q0 + row) * DIM + u);
        *(uint4*)&ql[row * AKP + u] = *(const uint4*)(Qlb + (size_t)(q0 + row) * DIM + u);
    }

    float o[2][8][4];
    float m[4], l[4];
    #pragma unroll
    for (int im = 0; im < 2; im++)
        #pragma unroll
        for (int n = 0; n < 8; n++)
            #pragma unroll
            for (int e = 0; e < 4; e++)
                o[im][n][e] = 0.0f;
    #pragma unroll
    for (int i = 0; i < 4; i++) { m[i] = -INFINITY; l[i] = 0.0f; }

    __syncthreads();

    const int wq0 = q0 + wid * 32;
    const int ntiles = 2 * qt + 2;

    for (int kvt = 0; kvt < ntiles; kvt++) {
        const int kv0 = kvt * 64;
        // stage K/V planes (64 x 64 halves each, 4 planes)
        #pragma unroll
        for (int i = 0; i < 4; i++) {
            int pos = tid + i * 128;
            int row = pos >> 3;
            int u   = (pos & 7) * 8;
            size_t goff = (size_t)(kv0 + row) * DIM + u;
            *(uint4*)&kh[row * AKP + u] = *(const uint4*)(Khb + goff);
            *(uint4*)&kl[row * AKP + u] = *(const uint4*)(Klb + goff);
            *(uint4*)&vh[row * AKP + u] = *(const uint4*)(Vhb + goff);
            *(uint4*)&vl[row * AKP + u] = *(const uint4*)(Vlb + goff);
        }
        __syncthreads();

        const bool active = (kv0 <= wq0 + 31);
        if (active) {
            // ---- S = Q K^T ----
            float s[2][8][4];
            #pragma unroll
            for (int im = 0; im < 2; im++)
                #pragma unroll
                for (int n = 0; n < 8; n++)
                    #pragma unroll
                    for (int e = 0; e < 4; e++)
                        s[im][n][e] = 0.0f;

            #pragma unroll
            for (int ks = 0; ks < 4; ks++) {
                const int kk = ks * 16;
                uint32_t ahi[2][4], alo[2][4];
                #pragma unroll
                for (int im = 0; im < 2; im++) {
                    int rb = wid * 32 + im * 16;
                    ahi[im][0] = *(const uint32_t*)&qh[(rb + g) * AKP + kk + 2 * t];
                    ahi[im][1] = *(const uint32_t*)&qh[(rb + 8 + g) * AKP + kk + 2 * t];
                    ahi[im][2] = *(const uint32_t*)&qh[(rb + g) * AKP + kk + 8 + 2 * t];
                    ahi[im][3] = *(const uint32_t*)&qh[(rb + 8 + g) * AKP + kk + 8 + 2 * t];
                    alo[im][0] = *(const uint32_t*)&ql[(rb + g) * AKP + kk + 2 * t];
                    alo[im][1] = *(const uint32_t*)&ql[(rb + 8 + g) * AKP + kk + 2 * t];
                    alo[im][2] = *(const uint32_t*)&ql[(rb + g) * AKP + kk + 8 + 2 * t];
                    alo[im][3] = *(const uint32_t*)&ql[(rb + 8 + g) * AKP + kk + 8 + 2 * t];
                }
                #pragma unroll
                for (int n = 0; n < 8; n++) {
                    int col = n * 8 + g;
                    uint32_t bhi[2], blo[2];
                    bhi[0] = *(const uint32_t*)&kh[col * AKP + kk + 2 * t];
                    bhi[1] = *(const uint32_t*)&kh[col * AKP + kk + 8 + 2 * t];
                    blo[0] = *(const uint32_t*)&kl[col * AKP + kk + 2 * t];
                    blo[1] = *(const uint32_t*)&kl[col * AKP + kk + 8 + 2 * t];
                    #pragma unroll
                    for (int im = 0; im < 2; im++) {
                        mma16(s[im][n], ahi[im], bhi);
                        mma16(s[im][n], ahi[im], blo);
                        mma16(s[im][n], alo[im], bhi);
                    }
                }
            }

            // ---- scale + causal mask ----
            const bool needmask = (kv0 + 63) > wq0;
            #pragma unroll
            for (int im = 0; im < 2; im++)
                #pragma unroll
                for (int n = 0; n < 8; n++)
                    #pragma unroll
                    for (int e = 0; e < 4; e++) {
                        float v = s[im][n][e] * 0.125f;
                        if (needmask) {
                            int col = kv0 + n * 8 + 2 * t + (e & 1);
                            int row = wq0 + im * 16 + g + ((e >> 1) * 8);
                            if (col > row) v = -1e30f;
                        }
                        s[im][n][e] = v;
                    }

            // ---- streaming softmax ----
            #pragma unroll
            for (int im = 0; im < 2; im++) {
                #pragma unroll
                for (int hh = 0; hh < 2; hh++) {
                    int ri = im * 2 + hh;
                    float rowmax = -INFINITY;
                    #pragma unroll
                    for (int n = 0; n < 8; n++) {
                        rowmax = fmaxf(rowmax, s[im][n][hh * 2 + 0]);
                        rowmax = fmaxf(rowmax, s[im][n][hh * 2 + 1]);
                    }
                    rowmax = fmaxf(rowmax, __shfl_xor_sync(0xffffffffu, rowmax, 1));
                    rowmax = fmaxf(rowmax, __shfl_xor_sync(0xffffffffu, rowmax, 2));
                    float mnew = fmaxf(m[ri], rowmax);
                    float alpha = __expf(m[ri] - mnew);
                    m[ri] = mnew;
                    float rs = 0.0f;
                    #pragma unroll
                    for (int n = 0; n < 8; n++) {
                        float p0 = __expf(s[im][n][hh * 2 + 0] - mnew);
                        float p1 = __expf(s[im][n][hh * 2 + 1] - mnew);
                        s[im][n][hh * 2 + 0] = p0;
                        s[im][n][hh * 2 + 1] = p1;
                        rs += p0 + p1;
                    }
                    rs += __shfl_xor_sync(0xffffffffu, rs, 1);
                    rs += __shfl_xor_sync(0xffffffffu, rs, 2);
                    l[ri] = l[ri] * alpha + rs;
                    #pragma unroll
                    for (int n = 0; n < 8; n++) {
                        o[im][n][hh * 2 + 0] *= alpha;
                        o[im][n][hh * 2 + 1] *= alpha;
                    }
                }
            }

            // ---- split P (x256) into warp-private hi/lo planes ----
            #pragma unroll
            for (int im = 0; im < 2; im++) {
                int rb = wid * 32 + im * 16;
                #pragma unroll
                for (int n = 0; n < 8; n++) {
                    __half h0, l0, h1, l1;
                    splitf(s[im][n][0] * 256.0f, h0, l0);
                    splitf(s[im][n][1] * 256.0f, h1, l1);
                    *(__half2*)&ph[(rb + g) * AKP + n * 8 + 2 * t] = __halves2half2(h0, h1);
                    *(__half2*)&pl[(rb + g) * AKP + n * 8 + 2 * t] = __halves2half2(l0, l1);
                    splitf(s[im][n][2] * 256.0f, h0, l0);
                    splitf(s[im][n][3] * 256.0f, h1, l1);
                    *(__half2*)&ph[(rb + 8 + g) * AKP + n * 8 + 2 * t] = __halves2half2(h0, h1);
                    *(__half2*)&pl[(rb + 8 + g) * AKP + n * 8 + 2 * t] = __halves2half2(l0, l1);
                }
            }
            __syncwarp();

            // ---- O += P V  (V transposed at read via ldmatrix.trans) ----
            #pragma unroll
            for (int ks = 0; ks < 4; ks++) {
                const int kk = ks * 16;
                uint32_t ahi[2][4], alo[2][4];
                #pragma unroll
                for (int im = 0; im < 2; im++) {
                    int rb = wid * 32 + im * 16;
                    ahi[im][0] = *(const uint32_t*)&ph[(rb + g) * AKP + kk + 2 * t];
                    ahi[im][1] = *(const uint32_t*)&ph[(rb + 8 + g) * AKP + kk + 2 * t];
                    ahi[im][2] = *(const uint32_t*)&ph[(rb + g) * AKP + kk + 8 + 2 * t];
                    ahi[im][3] = *(const uint32_t*)&ph[(rb + 8 + g) * AKP + kk + 8 + 2 * t];
                    alo[im][0] = *(const uint32_t*)&pl[(rb + g) * AKP + kk + 2 * t];
                    alo[im][1] = *(const uint32_t*)&pl[(rb + 8 + g) * AKP + kk + 2 * t];
                    alo[im][2] = *(const uint32_t*)&pl[(rb + g) * AKP + kk + 8 + 2 * t];
                    alo[im][3] = *(const uint32_t*)&pl[(rb + 8 + g) * AKP + kk + 8 + 2 * t];
                }
                const int rml = kk + ((lane >> 3) & 1) * 8 + (lane & 7);
                #pragma unroll
                for (int nb = 0; nb < 4; nb++) {
                    const int cml = nb * 16 + (lane >> 4) * 8;
                    uint32_t va  = sb + (uint32_t)(OVH + rml * AKP + cml) * 2u;
                    uint32_t vb_ = sb + (uint32_t)(OVL + rml * AKP + cml) * 2u;
                    uint32_t h0, h1, h2, h3, l0, l1, l2, l3;
                    ldmx4t(h0, h1, h2, h3, va);
                    ldmx4t(l0, l1, l2, l3, vb_);
                    uint32_t bh0[2] = { h0, h1 }, bh1[2] = { h2, h3 };
                    uint32_t bl0[2] = { l0, l1 }, bl1[2] = { l2, l3 };
                    #pragma unroll
                    for (int im = 0; im < 2; im++) {
                        mma16(o[im][2 * nb + 0], ahi[im], bh0);
                        mma16(o[im][2 * nb + 0], ahi[im], bl0);
                        mma16(o[im][2 * nb + 0], alo[im], bh0);
                        mma16(o[im][2 * nb + 1], ahi[im], bh1);
                        mma16(o[im][2 * nb + 1], ahi[im], bl1);
                        mma16(o[im][2 * nb + 1], alo[im], bh1);
                    }
                }
            }
        }
        __syncthreads();
    }

    // ---- epilogue: normalize (undo P x256), split, write O planes ----
    __half* Ohb = g_Oh + base;
    __half* Olb = g_Ol + base;
    #pragma unroll
    for (int im = 0; im < 2; im++) {
        int r0 = q0 + wid * 32 + im * 16 + g;
        int r1 = r0 + 8;
        float inv0 = 1.0f / (256.0f * l[im * 2 + 0]);
        float inv1 = 1.0f / (256.0f * l[im * 2 + 1]);
        #pragma unroll
        for (int n = 0; n < 8; n++) {
            int c = n * 8 + 2 * t;
            __half h0, l0_, h1, l1_;
            splitf(o[im][n][0] * inv0, h0, l0_);
            splitf(o[im][n][1] * inv0, h1, l1_);
            *(__half2*)&Ohb[(size_t)r0 * DIM + c] = __halves2half2(h0, h1);
            *(__half2*)&Olb[(size_t)r0 * DIM + c] = __halves2half2(l0_, l1_);
            splitf(o[im][n][2] * inv1, h0, l0_);
            splitf(o[im][n][3] * inv1, h1, l1_);
            *(__half2*)&Ohb[(size_t)r1 * DIM + c] = __halves2half2(h0, h1);
            *(__half2*)&Olb[(size_t)r1 * DIM + c] = __halves2half2(l0_, l1_);
        }
    }
}

// ---------------- launch ----------------
extern "C" void kernel_launch(void* const* d_in, const int* in_sizes, int n_in,
                              void* d_out, int out_size)
{
    const float* x  = (const float*)d_in[0];
    const float* WQ = (const float*)d_in[1];
    const float* WK = (const float*)d_in[2];
    const float* WV = (const float*)d_in[3];
    const float* WO = (const float*)d_in[4];
    const int*  pos = (const int*)d_in[5];
    float* out = (float*)d_out;

    cudaFuncSetAttribute(gemm_h2<0>, cudaFuncAttributeMaxDynamicSharedMemorySize, GEMM_SMEM);
    cudaFuncSetAttribute(gemm_h2<1>, cudaFuncAttributeMaxDynamicSharedMemorySize, GEMM_SMEM);
    cudaFuncSetAttribute(gemm_h2<2>, cudaFuncAttributeMaxDynamicSharedMemorySize, GEMM_SMEM);
    cudaFuncSetAttribute(gemm_h2<3>, cudaFuncAttributeMaxDynamicSharedMemorySize, GEMM_SMEM);
    cudaFuncSetAttribute(attn_h2_kernel, cudaFuncAttributeMaxDynamicSharedMemorySize, ATT_SMEM);

    rope_table_kernel<<<(SEQ * 32 + 255) / 256, 256>>>(pos);
    convert_x_kernel<<<(NROWS * DIM / 4 + 255) / 256, 256>>>(x);
    convert_w_kernel<<<(DIM * DIM / 4 + 255) / 256, 256>>>(WQ, 0);
    convert_w_kernel<<<(DIM * DIM / 4 + 255) / 256, 256>>>(WK, 1);
    convert_w_kernel<<<(DIM * DIM / 4 + 255) / 256, 256>>>(WV, 2);
    convert_w_kernel<<<(DIM * DIM / 4 + 255) / 256, 256>>>(WO, 3);

    dim3 ggrid(DIM / 128, NROWS / 128);   // (8, 64)
    gemm_h2<0><<<ggrid, 256, GEMM_SMEM>>>(nullptr);
    gemm_h2<1><<<ggrid, 256, GEMM_SMEM>>>(nullptr);
    gemm_h2<2><<<ggrid, 256, GEMM_SMEM>>>(nullptr);

    attn_h2_kernel<<<dim3(SEQ / 128, BATCH * NHEAD), 128, ATT_SMEM>>>();

    gemm_h2<3><<<ggrid, 256, GEMM_SMEM>>>(out);
}

// round 7
// speedup vs baseline: 1.1336x; 1.1336x over previous
#include <cuda_runtime.h>
#include <cuda_fp16.h>
#include <math.h>
#include <stdint.h>

#define BATCH 4
#define SEQ   2048
#define DIM   1024
#define NHEAD 16
#define DH    64
#define NROWS (BATCH*SEQ)   // 8192

// ---------------- scratch (device globals) ----------------
__device__ __half g_Xh[(size_t)NROWS * DIM];
__device__ __half g_Xl[(size_t)NROWS * DIM];
__device__ __half g_Wh[(size_t)4 * DIM * DIM];
__device__ __half g_Wl[(size_t)4 * DIM * DIM];
__device__ __half g_Qh[(size_t)NROWS * DIM];
__device__ __half g_Ql[(size_t)NROWS * DIM];
__device__ __half g_Kh[(size_t)NROWS * DIM];
__device__ __half g_Kl[(size_t)NROWS * DIM];
__device__ __half g_Vh[(size_t)NROWS * DIM];
__device__ __half g_Vl[(size_t)NROWS * DIM];
__device__ __half g_Oh[(size_t)NROWS * DIM];
__device__ __half g_Ol[(size_t)NROWS * DIM];
__device__ float g_cos[SEQ * 32];
__device__ float g_sin[SEQ * 32];

// ---------------- helpers ----------------
__device__ __forceinline__ void splitf(float x, __half& h, __half& l) {
    h = __float2half_rn(x);
    l = __float2half_rn(x - __half2float(h));
}
__device__ __forceinline__ void mma16(float* c, const uint32_t* a, const uint32_t* b) {
    asm volatile(
        "mma.sync.aligned.m16n8k16.row.col.f32.f16.f16.f32 "
        "{%0,%1,%2,%3},{%4,%5,%6,%7},{%8,%9},{%0,%1,%2,%3};"
        : "+f"(c[0]), "+f"(c[1]), "+f"(c[2]), "+f"(c[3])
        : "r"(a[0]), "r"(a[1]), "r"(a[2]), "r"(a[3]), "r"(b[0]), "r"(b[1]));
}
__device__ __forceinline__ void ldmx4(uint32_t& d0, uint32_t& d1, uint32_t& d2, uint32_t& d3,
                                      uint32_t saddr) {
    asm volatile("ldmatrix.sync.aligned.m8n8.x4.shared.b16 {%0,%1,%2,%3}, [%4];"
                 : "=r"(d0), "=r"(d1), "=r"(d2), "=r"(d3) : "r"(saddr));
}
__device__ __forceinline__ void ldmx4t(uint32_t& d0, uint32_t& d1, uint32_t& d2, uint32_t& d3,
                                       uint32_t saddr) {
    asm volatile("ldmatrix.sync.aligned.m8n8.x4.trans.shared.b16 {%0,%1,%2,%3}, [%4];"
                 : "=r"(d0), "=r"(d1), "=r"(d2), "=r"(d3) : "r"(saddr));
}
__device__ __forceinline__ void cp16h(__half* dst, const __half* src) {
    unsigned s = (unsigned)__cvta_generic_to_shared(dst);
    asm volatile("cp.async.ca.shared.global [%0], [%1], 16;" :: "r"(s), "l"(src));
}
__device__ __forceinline__ void cp_commit() { asm volatile("cp.async.commit_group;"); }
template<int N>
__device__ __forceinline__ void cp_wait() { asm volatile("cp.async.wait_group %0;" :: "n"(N)); }

// ---------------- RoPE table ----------------
__global__ void rope_table_kernel(const int* __restrict__ pos)
{
    int idx = blockIdx.x * blockDim.x + threadIdx.x;
    if (idx >= SEQ * 32) return;
    int s = idx >> 5;
    int p = idx & 31;
    float inv = powf(10000.0f, -(float)(2 * p) / (float)DH);
    float ang = (float)pos[s] * inv;
    float sv, cv;
    sincosf(ang, &sv, &cv);
    g_cos[idx] = cv;
    g_sin[idx] = sv;
}

// ---------------- converters ----------------
__global__ void convert_x_kernel(const float* __restrict__ x)
{
    size_t i = ((size_t)blockIdx.x * blockDim.x + threadIdx.x) * 4;
    if (i >= (size_t)NROWS * DIM) return;
    float4 v = *(const float4*)(x + i);
    __half h0, l0, h1, l1, h2, l2, h3, l3;
    splitf(v.x, h0, l0); splitf(v.y, h1, l1);
    splitf(v.z, h2, l2); splitf(v.w, h3, l3);
    *(__half2*)&g_Xh[i]     = __halves2half2(h0, h1);
    *(__half2*)&g_Xh[i + 2] = __halves2half2(h2, h3);
    *(__half2*)&g_Xl[i]     = __halves2half2(l0, l1);
    *(__half2*)&g_Xl[i + 2] = __halves2half2(l2, l3);
}
__global__ void convert_w_kernel(const float* __restrict__ W, int widx)
{
    size_t i = ((size_t)blockIdx.x * blockDim.x + threadIdx.x) * 4;
    if (i >= (size_t)DIM * DIM) return;
    size_t o = (size_t)widx * DIM * DIM + i;
    float4 v = *(const float4*)(W + i);
    v.x *= 256.0f; v.y *= 256.0f; v.z *= 256.0f; v.w *= 256.0f;
    __half h0, l0, h1, l1, h2, l2, h3, l3;
    splitf(v.x, h0, l0); splitf(v.y, h1, l1);
    splitf(v.z, h2, l2); splitf(v.w, h3, l3);
    *(__half2*)&g_Wh[o]     = __halves2half2(h0, h1);
    *(__half2*)&g_Wh[o + 2] = __halves2half2(h2, h3);
    *(__half2*)&g_Wl[o]     = __halves2half2(l0, l1);
    *(__half2*)&g_Wl[o + 2] = __halves2half2(l2, l3);
}

// ---------------- fp16x2 GEMM: ldmatrix fragments + cp.async pipeline ----------------
// MODE: 0 -> Qh/Ql (RoPE), 1 -> Kh/Kl (RoPE), 2 -> Vh/Vl, 3 -> A=Oh/Ol, C=Cout fp32
#define GKP 40
#define GPL (128 * GKP)
#define GSTG (4 * GPL)
#define GEMM_SMEM (2 * GSTG * 2)  // 81920 B

template<int MODE>
__global__ void __launch_bounds__(256, 2) gemm_h2(float* __restrict__ Cout)
{
    extern __shared__ __half smh[];
    const __half* Aph = (MODE == 3) ? g_Oh : g_Xh;
    const __half* Apl = (MODE == 3) ? g_Ol : g_Xl;
    const __half* Bph = g_Wh + (size_t)MODE * DIM * DIM;
    const __half* Bpl = g_Wl + (size_t)MODE * DIM * DIM;
    const uint32_t sb = (uint32_t)__cvta_generic_to_shared(smh);

    const int tid  = threadIdx.x;
    const int lane = tid & 31;
    const int wid  = tid >> 5;
    const int g    = lane >> 2;
    const int t    = lane & 3;
    const int wm   = wid & 1;
    const int wn   = wid >> 1;

    const int row0 = blockIdx.y * 128;
    const int col0 = blockIdx.x * 128;

    // ldmatrix lane-address components
    const int a_r = ((lane >> 3) & 1) * 8 + (lane & 7);  // row within 16
    const int a_c = ((lane >> 4) & 1) * 8;               // k-col select
    const int b_rsel = (lane >> 4);                      // n within pair
    const int b_r = (lane & 7);
    const int b_c = ((lane >> 3) & 1) * 8;

    float acc[4][4][4];
    #pragma unroll
    for (int im = 0; im < 4; im++)
        #pragma unroll
        for (int in = 0; in < 4; in++)
            #pragma unroll
            for (int e = 0; e < 4; e++)
                acc[im][in][e] = 0.0f;

    auto load_stage = [&](int st, int kt) {
        const int k0 = kt * 32;
        #pragma unroll
        for (int i = 0; i < 8; i++) {
            int uidx = tid + i * 256;
            int p    = uidx >> 9;
            int w    = uidx & 511;
            int row  = w >> 2;
            int un   = (w & 3) * 8;
            const __half* src;
            if (p == 0)      src = Aph + (size_t)(row0 + row) * DIM + k0 + un;
            else if (p == 1) src = Apl + (size_t)(row0 + row) * DIM + k0 + un;
            else if (p == 2) src = Bph + (size_t)(col0 + row) * DIM + k0 + un;
            else             src = Bpl + (size_t)(col0 + row) * DIM + k0 + un;
            cp16h(&smh[st * GSTG + p * GPL + row * GKP + un], src);
        }
    };

    load_stage(0, 0);
    cp_commit();

    const int NKT = DIM / 32;
    for (int kt = 0; kt < NKT; kt++) {
        const int st = kt & 1;
        cp_wait<0>();
        __syncthreads();
        if (kt + 1 < NKT) { load_stage(st ^ 1, kt + 1); cp_commit(); }

        const uint32_t s0 = sb + (uint32_t)(st * GSTG) * 2u;   // Ah base (bytes)
        #pragma unroll
        for (int kq = 0; kq < 2; kq++) {
            const int kk = kq * 16;
            // B fragments: 2 pairs x 2 planes = 4 ldmatrix.x4
            uint32_t bh[4][2], bl[4][2];
            #pragma unroll
            for (int q = 0; q < 2; q++) {
                uint32_t boff = (uint32_t)((wn * 32 + (2 * q + b_rsel) * 8 + b_r) * GKP
                                           + kk + b_c) * 2u;
                ldmx4(bh[2*q][0], bh[2*q][1], bh[2*q+1][0], bh[2*q+1][1],
                      s0 + (uint32_t)(2 * GPL) * 2u + boff);
                ldmx4(bl[2*q][0], bl[2*q][1], bl[2*q+1][0], bl[2*q+1][1],
                      s0 + (uint32_t)(3 * GPL) * 2u + boff);
            }
            #pragma unroll
            for (int im = 0; im < 4; im++) {
                uint32_t aoff = (uint32_t)((wm * 64 + im * 16 + a_r) * GKP + kk + a_c) * 2u;
                uint32_t ahi[4], alo[4];
                ldmx4(ahi[0], ahi[1], ahi[2], ahi[3], s0 + aoff);
                ldmx4(alo[0], alo[1], alo[2], alo[3], s0 + (uint32_t)GPL * 2u + aoff);
                #pragma unroll
                for (int in = 0; in < 4; in++) {
                    mma16(acc[im][in], ahi, bh[in]);
                    mma16(acc[im][in], ahi, bl[in]);
                    mma16(acc[im][in], alo, bh[in]);
                }
            }
        }
        __syncthreads();
    }

    const float sc = 1.0f / 256.0f;
    #pragma unroll
    for (int im = 0; im < 4; im++) {
        int r0 = row0 + wm * 64 + im * 16 + g;
        int r1 = r0 + 8;
        #pragma unroll
        for (int in = 0; in < 4; in++) {
            int c = col0 + wn * 32 + in * 8 + 2 * t;
            float v0 = acc[im][in][0] * sc, v1 = acc[im][in][1] * sc;
            float v2 = acc[im][in][2] * sc, v3 = acc[im][in][3] * sc;
            if (MODE == 3) {
                float2 o0 = { v0, v1 };
                float2 o1 = { v2, v3 };
                *(float2*)(Cout + (size_t)r0 * DIM + c) = o0;
                *(float2*)(Cout + (size_t)r1 * DIM + c) = o1;
            } else {
                if (MODE <= 1) {
                    int p = (c & 63) >> 1;
                    int s0i = r0 & (SEQ - 1);
                    int s1i = r1 & (SEQ - 1);
                    float cv0 = g_cos[s0i * 32 + p], sv0 = g_sin[s0i * 32 + p];
                    float cv1 = g_cos[s1i * 32 + p], sv1 = g_sin[s1i * 32 + p];
                    float n0 = v0 * cv0 - v1 * sv0, n1 = v0 * sv0 + v1 * cv0;
                    float n2 = v2 * cv1 - v3 * sv1, n3 = v2 * sv1 + v3 * cv1;
                    v0 = n0; v1 = n1; v2 = n2; v3 = n3;
                }
                __half* Ch = (MODE == 0) ? g_Qh : (MODE == 1) ? g_Kh : g_Vh;
                __half* Cl = (MODE == 0) ? g_Ql : (MODE == 1) ? g_Kl : g_Vl;
                __half h0, l0, h1, l1;
                splitf(v0, h0, l0); splitf(v1, h1, l1);
                *(__half2*)&Ch[(size_t)r0 * DIM + c] = __halves2half2(h0, h1);
                *(__half2*)&Cl[(size_t)r0 * DIM + c] = __halves2half2(l0, l1);
                splitf(v2, h0, l0); splitf(v3, h1, l1);
                *(__half2*)&Ch[(size_t)r1 * DIM + c] = __halves2half2(h0, h1);
                *(__half2*)&Cl[(size_t)r1 * DIM + c] = __halves2half2(l0, l1);
            }
        }
    }
}

// ---------------- flash attention: 8 warps, ldmatrix, cp.async KV pipeline ----------------
#define AKP 72
#define OQH 0
#define OQL (128 * AKP)                       // 9216
#define OKV0 (2 * 128 * AKP)                  // 18432
#define KVSTG (4 * 64 * AKP)                  // 18432 halves per stage
#define OPH (OKV0 + 2 * KVSTG)                // 55296
#define OPL (OPH + 128 * AKP)                 // 64512
#define ATT_SMEM ((OPL + 128 * AKP) * 2)      // 147456 B

__global__ void __launch_bounds__(256, 1) attn_h2_kernel()
{
    extern __shared__ __half smh[];
    __half* qh = smh + OQH;  __half* ql = smh + OQL;
    __half* ph = smh + OPH;  __half* pl = smh + OPL;
    const uint32_t sb = (uint32_t)__cvta_generic_to_shared(smh);

    const int tid  = threadIdx.x;
    const int lane = tid & 31;
    const int wid  = tid >> 5;   // 0..7
    const int g    = lane >> 2;
    const int t    = lane & 3;

    const int qt = (int)gridDim.x - 1 - (int)blockIdx.x;  // heavy tiles first
    const int q0 = qt * 128;
    const int bh_ = blockIdx.y;
    const int b  = bh_ >> 4;
    const int h  = bh_ & 15;

    const size_t base = (size_t)b * SEQ * DIM + h * DH;
    const __half* Qhb = g_Qh + base;  const __half* Qlb = g_Ql + base;
    const __half* Khb = g_Kh + base;  const __half* Klb = g_Kl + base;
    const __half* Vhb = g_Vh + base;  const __half* Vlb = g_Vl + base;

    // ldmatrix lane components
    const int a_r = ((lane >> 3) & 1) * 8 + (lane & 7);
    const int a_c = ((lane >> 4) & 1) * 8;
    const int b_rsel = (lane >> 4);
    const int b_r = (lane & 7);
    const int b_c = ((lane >> 3) & 1) * 8;

    // load Q planes (128 x 64 halves each): 2048 16B units / 256 thr = 8
    #pragma unroll
    for (int i = 0; i < 8; i++) {
        int pos = tid + i * 256;
        int pl_ = pos >> 10;              // 0..1
        int w   = pos & 1023;
        int row = w >> 3;
        int u   = (w & 7) * 8;
        const __half* src = (pl_ == 0) ? Qhb : Qlb;
        __half* dst = (pl_ == 0) ? qh : ql;
        *(uint4*)&dst[row * AKP + u] = *(const uint4*)(src + (size_t)(q0 + row) * DIM + u);
    }

    auto load_kv = [&](int st, int kvt) {
        const int kv0 = kvt * 64;
        __half* kvbase = smh + OKV0 + st * KVSTG;
        #pragma unroll
        for (int i = 0; i < 8; i++) {
            int uidx = tid + i * 256;
            int p    = uidx >> 9;          // plane: kh,kl,vh,vl
            int w    = uidx & 511;
            int row  = w >> 3;
            int u    = (w & 7) * 8;
            const __half* src;
            if (p == 0)      src = Khb;
            else if (p == 1) src = Klb;
            else if (p == 2) src = Vhb;
            else             src = Vlb;
            cp16h(&kvbase[p * 64 * AKP + row * AKP + u],
                  src + (size_t)(kv0 + row) * DIM + u);
        }
    };

    float o[8][4];
    float m[2], l[2];
    #pragma unroll
    for (int n = 0; n < 8; n++)
        #pragma unroll
        for (int e = 0; e < 4; e++)
            o[n][e] = 0.0f;
    m[0] = m[1] = -INFINITY;
    l[0] = l[1] = 0.0f;

    const int rb  = wid * 16;
    const int wq0 = q0 + rb;
    const int ntiles = 2 * qt + 2;

    load_kv(0, 0);
    cp_commit();
    __syncthreads();   // Q planes ready

    for (int kvt = 0; kvt < ntiles; kvt++) {
        const int st = kvt & 1;
        const int kv0 = kvt * 64;
        cp_wait<0>();
        __syncthreads();
        if (kvt + 1 < ntiles) { load_kv(st ^ 1, kvt + 1); cp_commit(); }

        const uint32_t kvb = sb + (uint32_t)(OKV0 + st * KVSTG) * 2u;  // kh base bytes
        const uint32_t khB = kvb;
        const uint32_t klB = kvb + (uint32_t)(64 * AKP) * 2u;
        const uint32_t vhB = kvb + (uint32_t)(2 * 64 * AKP) * 2u;
        const uint32_t vlB = kvb + (uint32_t)(3 * 64 * AKP) * 2u;

        const bool active = (kv0 <= wq0 + 15);
        if (active) {
            // ---- S = Q K^T ----
            float s[8][4];
            #pragma unroll
            for (int n = 0; n < 8; n++)
                #pragma unroll
                for (int e = 0; e < 4; e++)
                    s[n][e] = 0.0f;

            #pragma unroll
            for (int ks = 0; ks < 4; ks++) {
                const int kk = ks * 16;
                uint32_t aoff = (uint32_t)((rb + a_r) * AKP + kk + a_c) * 2u;
                uint32_t ahi[4], alo[4];
                ldmx4(ahi[0], ahi[1], ahi[2], ahi[3], sb + (uint32_t)(OQH * 2) + aoff);
                ldmx4(alo[0], alo[1], alo[2], alo[3], sb + (uint32_t)(OQL * 2) + aoff);
                uint32_t bh[8][2], bl[8][2];
                #pragma unroll
                for (int q = 0; q < 4; q++) {
                    uint32_t boff = (uint32_t)(((2 * q + b_rsel) * 8 + b_r) * AKP
                                               + kk + b_c) * 2u;
                    ldmx4(bh[2*q][0], bh[2*q][1], bh[2*q+1][0], bh[2*q+1][1], khB + boff);
                    ldmx4(bl[2*q][0], bl[2*q][1], bl[2*q+1][0], bl[2*q+1][1], klB + boff);
                }
                #pragma unroll
                for (int n = 0; n < 8; n++) {
                    mma16(s[n], ahi, bh[n]);
                    mma16(s[n], ahi, bl[n]);
                    mma16(s[n], alo, bh[n]);
                }
            }

            // ---- scale + causal mask ----
            const bool needmask = (kv0 + 63) > wq0;
            #pragma unroll
            for (int n = 0; n < 8; n++)
                #pragma unroll
                for (int e = 0; e < 4; e++) {
                    float v = s[n][e] * 0.125f;
                    if (needmask) {
                        int col = kv0 + n * 8 + 2 * t + (e & 1);
                        int row = wq0 + g + ((e >> 1) * 8);
                        if (col > row) v = -1e30f;
                    }
                    s[n][e] = v;
                }

            // ---- streaming softmax ----
            #pragma unroll
            for (int hh = 0; hh < 2; hh++) {
                float rowmax = -INFINITY;
                #pragma unroll
                for (int n = 0; n < 8; n++) {
                    rowmax = fmaxf(rowmax, s[n][hh * 2 + 0]);
                    rowmax = fmaxf(rowmax, s[n][hh * 2 + 1]);
                }
                rowmax = fmaxf(rowmax, __shfl_xor_sync(0xffffffffu, rowmax, 1));
                rowmax = fmaxf(rowmax, __shfl_xor_sync(0xffffffffu, rowmax, 2));
                float mnew = fmaxf(m[hh], rowmax);
                float alpha = __expf(m[hh] - mnew);
                m[hh] = mnew;
                float rs = 0.0f;
                #pragma unroll
                for (int n = 0; n < 8; n++) {
                    float p0 = __expf(s[n][hh * 2 + 0] - mnew);
                    float p1 = __expf(s[n][hh * 2 + 1] - mnew);
                    s[n][hh * 2 + 0] = p0;
                    s[n][hh * 2 + 1] = p1;
                    rs += p0 + p1;
                }
                rs += __shfl_xor_sync(0xffffffffu, rs, 1);
                rs += __shfl_xor_sync(0xffffffffu, rs, 2);
                l[hh] = l[hh] * alpha + rs;
                #pragma unroll
                for (int n = 0; n < 8; n++) {
                    o[n][hh * 2 + 0] *= alpha;
                    o[n][hh * 2 + 1] *= alpha;
                }
            }

            // ---- split P (x256) into warp-private hi/lo rows ----
            #pragma unroll
            for (int n = 0; n < 8; n++) {
                __half h0, l0_, h1, l1_;
                splitf(s[n][0] * 256.0f, h0, l0_);
                splitf(s[n][1] * 256.0f, h1, l1_);
                *(__half2*)&ph[(rb + g) * AKP + n * 8 + 2 * t] = __halves2half2(h0, h1);
                *(__half2*)&pl[(rb + g) * AKP + n * 8 + 2 * t] = __halves2half2(l0_, l1_);
                splitf(s[n][2] * 256.0f, h0, l0_);
                splitf(s[n][3] * 256.0f, h1, l1_);
                *(__half2*)&ph[(rb + 8 + g) * AKP + n * 8 + 2 * t] = __halves2half2(h0, h1);
                *(__half2*)&pl[(rb + 8 + g) * AKP + n * 8 + 2 * t] = __halves2half2(l0_, l1_);
            }
            __syncwarp();

            // ---- O += P V ----
            const int rml = ((lane >> 3) & 1) * 8 + (lane & 7);
            const int cml0 = (lane >> 4) * 8;
            #pragma unroll
            for (int ks = 0; ks < 4; ks++) {
                const int kk = ks * 16;
                uint32_t aoff = (uint32_t)((rb + a_r) * AKP + kk + a_c) * 2u;
                uint32_t ahi[4], alo[4];
                ldmx4(ahi[0], ahi[1], ahi[2], ahi[3], sb + (uint32_t)(OPH * 2) + aoff);
                ldmx4(alo[0], alo[1], alo[2], alo[3], sb + (uint32_t)(OPL * 2) + aoff);
                #pragma unroll
                for (int nb = 0; nb < 4; nb++) {
                    uint32_t voff = (uint32_t)((kk + rml) * AKP + nb * 16 + cml0) * 2u;
                    uint32_t h0, h1, h2, h3, l0_, l1_, l2_, l3_;
                    ldmx4t(h0, h1, h2, h3, vhB + voff);
                    ldmx4t(l0_, l1_, l2_, l3_, vlB + voff);
                    uint32_t bh0[2] = { h0, h1 }, bh1[2] = { h2, h3 };
                    uint32_t bl0[2] = { l0_, l1_ }, bl1[2] = { l2_, l3_ };
                    mma16(o[2 * nb + 0], ahi, bh0);
                    mma16(o[2 * nb + 0], ahi, bl0);
                    mma16(o[2 * nb + 0], alo, bh0);
                    mma16(o[2 * nb + 1], ahi, bh1);
                    mma16(o[2 * nb + 1], ahi, bl1);
                    mma16(o[2 * nb + 1], alo, bh1);
                }
            }
        }
        __syncthreads();
    }

    // ---- epilogue: normalize (undo P x256), split, write O planes ----
    __half* Ohb = g_Oh + base;
    __half* Olb = g_Ol + base;
    {
        int r0 = q0 + rb + g;
        int r1 = r0 + 8;
        float inv0 = 1.0f / (256.0f * l[0]);
        float inv1 = 1.0f / (256.0f * l[1]);
        #pragma unroll
        for (int n = 0; n < 8; n++) {
            int c = n * 8 + 2 * t;
            __half h0, l0_, h1, l1_;
            splitf(o[n][0] * inv0, h0, l0_);
            splitf(o[n][1] * inv0, h1, l1_);
            *(__half2*)&Ohb[(size_t)r0 * DIM + c] = __halves2half2(h0, h1);
            *(__half2*)&Olb[(size_t)r0 * DIM + c] = __halves2half2(l0_, l1_);
            splitf(o[n][2] * inv1, h0, l0_);
            splitf(o[n][3] * inv1, h1, l1_);
            *(__half2*)&Ohb[(size_t)r1 * DIM + c] = __halves2half2(h0, h1);
            *(__half2*)&Olb[(size_t)r1 * DIM + c] = __halves2half2(l0_, l1_);
        }
    }
}

// ---------------- launch ----------------
extern "C" void kernel_launch(void* const* d_in, const int* in_sizes, int n_in,
                              void* d_out, int out_size)
{
    const float* x  = (const float*)d_in[0];
    const float* WQ = (const float*)d_in[1];
    const float* WK = (const float*)d_in[2];
    const float* WV = (const float*)d_in[3];
    const float* WO = (const float*)d_in[4];
    const int*  pos = (const int*)d_in[5];
    float* out = (float*)d_out;

    cudaFuncSetAttribute(gemm_h2<0>, cudaFuncAttributeMaxDynamicSharedMemorySize, GEMM_SMEM);
    cudaFuncSetAttribute(gemm_h2<1>, cudaFuncAttributeMaxDynamicSharedMemorySize, GEMM_SMEM);
    cudaFuncSetAttribute(gemm_h2<2>, cudaFuncAttributeMaxDynamicSharedMemorySize, GEMM_SMEM);
    cudaFuncSetAttribute(gemm_h2<3>, cudaFuncAttributeMaxDynamicSharedMemorySize, GEMM_SMEM);
    cudaFuncSetAttribute(attn_h2_kernel, cudaFuncAttributeMaxDynamicSharedMemorySize, ATT_SMEM);

    rope_table_kernel<<<(SEQ * 32 + 255) / 256, 256>>>(pos);
    convert_x_kernel<<<(NROWS * DIM / 4 + 255) / 256, 256>>>(x);
    convert_w_kernel<<<(DIM * DIM / 4 + 255) / 256, 256>>>(WQ, 0);
    convert_w_kernel<<<(DIM * DIM / 4 + 255) / 256, 256>>>(WK, 1);
    convert_w_kernel<<<(DIM * DIM / 4 + 255) / 256, 256>>>(WV, 2);
    convert_w_kernel<<<(DIM * DIM / 4 + 255) / 256, 256>>>(WO, 3);

    dim3 ggrid(DIM / 128, NROWS / 128);   // (8, 64)
    gemm_h2<0><<<ggrid, 256, GEMM_SMEM>>>(nullptr);
    gemm_h2<1><<<ggrid, 256, GEMM_SMEM>>>(nullptr);
    gemm_h2<2><<<ggrid, 256, GEMM_SMEM>>>(nullptr);

    attn_h2_kernel<<<dim3(SEQ / 128, BATCH * NHEAD), 256, ATT_SMEM>>>();

    gemm_h2<3><<<ggrid, 256, GEMM_SMEM>>>(out);
}

// round 8
// speedup vs baseline: 1.1425x; 1.0079x over previous
#include <cuda_runtime.h>
#include <cuda_fp16.h>
#include <math.h>
#include <stdint.h>

#define BATCH 4
#define SEQ   2048
#define DIM   1024
#define NHEAD 16
#define DH    64
#define NROWS (BATCH*SEQ)   // 8192

// ---------------- scratch (device globals) ----------------
__device__ __half g_Xh[(size_t)NROWS * DIM];
__device__ __half g_Xl[(size_t)NROWS * DIM];
__device__ __half g_Wh[(size_t)4 * DIM * DIM];
__device__ __half g_Wl[(size_t)4 * DIM * DIM];
__device__ __half g_Qh[(size_t)NROWS * DIM];
__device__ __half g_Ql[(size_t)NROWS * DIM];
__device__ __half g_Kh[(size_t)NROWS * DIM];
__device__ __half g_Kl[(size_t)NROWS * DIM];
__device__ __half g_Vh[(size_t)NROWS * DIM];
__device__ __half g_Vl[(size_t)NROWS * DIM];
__device__ __half g_Oh[(size_t)NROWS * DIM];
__device__ __half g_Ol[(size_t)NROWS * DIM];
__device__ float g_cos[SEQ * 32];
__device__ float g_sin[SEQ * 32];

// ---------------- helpers ----------------
__device__ __forceinline__ void splitf(float x, __half& h, __half& l) {
    h = __float2half_rn(x);
    l = __float2half_rn(x - __half2float(h));
}
__device__ __forceinline__ uint32_t pack2(__half a, __half b) {
    __half2 hh = __halves2half2(a, b);
    return *(uint32_t*)&hh;
}
__device__ __forceinline__ void mma16(float* c, const uint32_t* a, const uint32_t* b) {
    asm volatile(
        "mma.sync.aligned.m16n8k16.row.col.f32.f16.f16.f32 "
        "{%0,%1,%2,%3},{%4,%5,%6,%7},{%8,%9},{%0,%1,%2,%3};"
        : "+f"(c[0]), "+f"(c[1]), "+f"(c[2]), "+f"(c[3])
        : "r"(a[0]), "r"(a[1]), "r"(a[2]), "r"(a[3]), "r"(b[0]), "r"(b[1]));
}
__device__ __forceinline__ void ldmx4(uint32_t& d0, uint32_t& d1, uint32_t& d2, uint32_t& d3,
                                      uint32_t saddr) {
    asm volatile("ldmatrix.sync.aligned.m8n8.x4.shared.b16 {%0,%1,%2,%3}, [%4];"
                 : "=r"(d0), "=r"(d1), "=r"(d2), "=r"(d3) : "r"(saddr));
}
__device__ __forceinline__ void ldmx4t(uint32_t& d0, uint32_t& d1, uint32_t& d2, uint32_t& d3,
                                       uint32_t saddr) {
    asm volatile("ldmatrix.sync.aligned.m8n8.x4.trans.shared.b16 {%0,%1,%2,%3}, [%4];"
                 : "=r"(d0), "=r"(d1), "=r"(d2), "=r"(d3) : "r"(saddr));
}
__device__ __forceinline__ void cp16h(__half* dst, const __half* src) {
    unsigned s = (unsigned)__cvta_generic_to_shared(dst);
    asm volatile("cp.async.ca.shared.global [%0], [%1], 16;" :: "r"(s), "l"(src));
}
__device__ __forceinline__ void cp_commit() { asm volatile("cp.async.commit_group;"); }
template<int N>
__device__ __forceinline__ void cp_wait() { asm volatile("cp.async.wait_group %0;" :: "n"(N)); }

// ---------------- RoPE table ----------------
__global__ void rope_table_kernel(const int* __restrict__ pos)
{
    int idx = blockIdx.x * blockDim.x + threadIdx.x;
    if (idx >= SEQ * 32) return;
    int s = idx >> 5;
    int p = idx & 31;
    float inv = powf(10000.0f, -(float)(2 * p) / (float)DH);
    float ang = (float)pos[s] * inv;
    float sv, cv;
    sincosf(ang, &sv, &cv);
    g_cos[idx] = cv;
    g_sin[idx] = sv;
}

// ---------------- converters ----------------
__global__ void convert_x_kernel(const float* __restrict__ x)
{
    size_t i = ((size_t)blockIdx.x * blockDim.x + threadIdx.x) * 4;
    if (i >= (size_t)NROWS * DIM) return;
    float4 v = *(const float4*)(x + i);
    __half h0, l0, h1, l1, h2, l2, h3, l3;
    splitf(v.x, h0, l0); splitf(v.y, h1, l1);
    splitf(v.z, h2, l2); splitf(v.w, h3, l3);
    *(__half2*)&g_Xh[i]     = __halves2half2(h0, h1);
    *(__half2*)&g_Xh[i + 2] = __halves2half2(h2, h3);
    *(__half2*)&g_Xl[i]     = __halves2half2(l0, l1);
    *(__half2*)&g_Xl[i + 2] = __halves2half2(l2, l3);
}
__global__ void convert_w_kernel(const float* __restrict__ W, int widx)
{
    size_t i = ((size_t)blockIdx.x * blockDim.x + threadIdx.x) * 4;
    if (i >= (size_t)DIM * DIM) return;
    size_t o = (size_t)widx * DIM * DIM + i;
    float4 v = *(const float4*)(W + i);
    v.x *= 256.0f; v.y *= 256.0f; v.z *= 256.0f; v.w *= 256.0f;
    __half h0, l0, h1, l1, h2, l2, h3, l3;
    splitf(v.x, h0, l0); splitf(v.y, h1, l1);
    splitf(v.z, h2, l2); splitf(v.w, h3, l3);
    *(__half2*)&g_Wh[o]     = __halves2half2(h0, h1);
    *(__half2*)&g_Wh[o + 2] = __halves2half2(h2, h3);
    *(__half2*)&g_Wl[o]     = __halves2half2(l0, l1);
    *(__half2*)&g_Wl[o + 2] = __halves2half2(l2, l3);
}

// ---------------- fp16x2 GEMM: ldmatrix fragments + cp.async pipeline ----------------
// MODE: 0 -> Qh/Ql (RoPE), 1 -> Kh/Kl (RoPE), 2 -> Vh/Vl, 3 -> A=Oh/Ol, C=Cout fp32
#define GKP 40
#define GPL (128 * GKP)
#define GSTG (4 * GPL)
#define GEMM_SMEM (2 * GSTG * 2)  // 81920 B

template<int MODE>
__global__ void __launch_bounds__(256, 2) gemm_h2(float* __restrict__ Cout)
{
    extern __shared__ __half smh[];
    const __half* Aph = (MODE == 3) ? g_Oh : g_Xh;
    const __half* Apl = (MODE == 3) ? g_Ol : g_Xl;
    const __half* Bph = g_Wh + (size_t)MODE * DIM * DIM;
    const __half* Bpl = g_Wl + (size_t)MODE * DIM * DIM;
    const uint32_t sb = (uint32_t)__cvta_generic_to_shared(smh);

    const int tid  = threadIdx.x;
    const int lane = tid & 31;
    const int wid  = tid >> 5;
    const int g    = lane >> 2;
    const int t    = lane & 3;
    const int wm   = wid & 1;
    const int wn   = wid >> 1;

    const int row0 = blockIdx.y * 128;
    const int col0 = blockIdx.x * 128;

    const int a_r = ((lane >> 3) & 1) * 8 + (lane & 7);
    const int a_c = ((lane >> 4) & 1) * 8;
    const int b_rsel = (lane >> 4);
    const int b_r = (lane & 7);
    const int b_c = ((lane >> 3) & 1) * 8;

    float acc[4][4][4];
    #pragma unroll
    for (int im = 0; im < 4; im++)
        #pragma unroll
        for (int in = 0; in < 4; in++)
            #pragma unroll
            for (int e = 0; e < 4; e++)
                acc[im][in][e] = 0.0f;

    auto load_stage = [&](int st, int kt) {
        const int k0 = kt * 32;
        #pragma unroll
        for (int i = 0; i < 8; i++) {
            int uidx = tid + i * 256;
            int p    = uidx >> 9;
            int w    = uidx & 511;
            int row  = w >> 2;
            int un   = (w & 3) * 8;
            const __half* src;
            if (p == 0)      src = Aph + (size_t)(row0 + row) * DIM + k0 + un;
            else if (p == 1) src = Apl + (size_t)(row0 + row) * DIM + k0 + un;
            else if (p == 2) src = Bph + (size_t)(col0 + row) * DIM + k0 + un;
            else             src = Bpl + (size_t)(col0 + row) * DIM + k0 + un;
            cp16h(&smh[st * GSTG + p * GPL + row * GKP + un], src);
        }
    };

    load_stage(0, 0);
    cp_commit();

    const int NKT = DIM / 32;
    for (int kt = 0; kt < NKT; kt++) {
        const int st = kt & 1;
        cp_wait<0>();
        __syncthreads();
        if (kt + 1 < NKT) { load_stage(st ^ 1, kt + 1); cp_commit(); }

        const uint32_t s0 = sb + (uint32_t)(st * GSTG) * 2u;
        #pragma unroll
        for (int kq = 0; kq < 2; kq++) {
            const int kk = kq * 16;
            uint32_t bh[4][2], bl[4][2];
            #pragma unroll
            for (int q = 0; q < 2; q++) {
                uint32_t boff = (uint32_t)((wn * 32 + (2 * q + b_rsel) * 8 + b_r) * GKP
                                           + kk + b_c) * 2u;
                ldmx4(bh[2*q][0], bh[2*q][1], bh[2*q+1][0], bh[2*q+1][1],
                      s0 + (uint32_t)(2 * GPL) * 2u + boff);
                ldmx4(bl[2*q][0], bl[2*q][1], bl[2*q+1][0], bl[2*q+1][1],
                      s0 + (uint32_t)(3 * GPL) * 2u + boff);
            }
            #pragma unroll
            for (int im = 0; im < 4; im++) {
                uint32_t aoff = (uint32_t)((wm * 64 + im * 16 + a_r) * GKP + kk + a_c) * 2u;
                uint32_t ahi[4], alo[4];
                ldmx4(ahi[0], ahi[1], ahi[2], ahi[3], s0 + aoff);
                ldmx4(alo[0], alo[1], alo[2], alo[3], s0 + (uint32_t)GPL * 2u + aoff);
                #pragma unroll
                for (int in = 0; in < 4; in++) {
                    mma16(acc[im][in], ahi, bh[in]);
                    mma16(acc[im][in], ahi, bl[in]);
                    mma16(acc[im][in], alo, bh[in]);
                }
            }
        }
        __syncthreads();
    }

    const float sc = 1.0f / 256.0f;
    #pragma unroll
    for (int im = 0; im < 4; im++) {
        int r0 = row0 + wm * 64 + im * 16 + g;
        int r1 = r0 + 8;
        #pragma unroll
        for (int in = 0; in < 4; in++) {
            int c = col0 + wn * 32 + in * 8 + 2 * t;
            float v0 = acc[im][in][0] * sc, v1 = acc[im][in][1] * sc;
            float v2 = acc[im][in][2] * sc, v3 = acc[im][in][3] * sc;
            if (MODE == 3) {
                float2 o0 = { v0, v1 };
                float2 o1 = { v2, v3 };
                *(float2*)(Cout + (size_t)r0 * DIM + c) = o0;
                *(float2*)(Cout + (size_t)r1 * DIM + c) = o1;
            } else {
                if (MODE <= 1) {
                    int p = (c & 63) >> 1;
                    int s0i = r0 & (SEQ - 1);
                    int s1i = r1 & (SEQ - 1);
                    float cv0 = g_cos[s0i * 32 + p], sv0 = g_sin[s0i * 32 + p];
                    float cv1 = g_cos[s1i * 32 + p], sv1 = g_sin[s1i * 32 + p];
                    float n0 = v0 * cv0 - v1 * sv0, n1 = v0 * sv0 + v1 * cv0;
                    float n2 = v2 * cv1 - v3 * sv1, n3 = v2 * sv1 + v3 * cv1;
                    v0 = n0; v1 = n1; v2 = n2; v3 = n3;
                }
                __half* Ch = (MODE == 0) ? g_Qh : (MODE == 1) ? g_Kh : g_Vh;
                __half* Cl = (MODE == 0) ? g_Ql : (MODE == 1) ? g_Kl : g_Vl;
                __half h0, l0, h1, l1;
                splitf(v0, h0, l0); splitf(v1, h1, l1);
                *(__half2*)&Ch[(size_t)r0 * DIM + c] = __halves2half2(h0, h1);
                *(__half2*)&Cl[(size_t)r0 * DIM + c] = __halves2half2(l0, l1);
                splitf(v2, h0, l0); splitf(v3, h1, l1);
                *(__half2*)&Ch[(size_t)r1 * DIM + c] = __halves2half2(h0, h1);
                *(__half2*)&Cl[(size_t)r1 * DIM + c] = __halves2half2(l0, l1);
            }
        }
    }
}

// ---------------- flash attention: 8 warps, P kept in registers ----------------
#define AKP 72
#define OQH 0
#define OQL (128 * AKP)                       // 9216
#define OKV0 (2 * 128 * AKP)                  // 18432
#define KVSTG (4 * 64 * AKP)                  // 18432 halves per stage
#define ATT_SMEM ((OKV0 + 2 * KVSTG) * 2)     // 110592 B

__global__ void __launch_bounds__(256, 2) attn_h2_kernel()
{
    extern __shared__ __half smh[];
    __half* qh = smh + OQH;  __half* ql = smh + OQL;
    const uint32_t sb = (uint32_t)__cvta_generic_to_shared(smh);

    const int tid  = threadIdx.x;
    const int lane = tid & 31;
    const int wid  = tid >> 5;   // 0..7
    const int g    = lane >> 2;
    const int t    = lane & 3;

    const int qt = (int)gridDim.x - 1 - (int)blockIdx.x;  // heavy tiles first
    const int q0 = qt * 128;
    const int bh_ = blockIdx.y;
    const int b  = bh_ >> 4;
    const int h  = bh_ & 15;

    const size_t base = (size_t)b * SEQ * DIM + h * DH;
    const __half* Qhb = g_Qh + base;  const __half* Qlb = g_Ql + base;
    const __half* Khb = g_Kh + base;  const __half* Klb = g_Kl + base;
    const __half* Vhb = g_Vh + base;  const __half* Vlb = g_Vl + base;

    const int a_r = ((lane >> 3) & 1) * 8 + (lane & 7);
    const int a_c = ((lane >> 4) & 1) * 8;
    const int b_rsel = (lane >> 4);
    const int b_r = (lane & 7);
    const int b_c = ((lane >> 3) & 1) * 8;

    // load Q planes (128 x 64 halves each): 2048 16B units / 256 thr = 8
    #pragma unroll
    for (int i = 0; i < 8; i++) {
        int pos = tid + i * 256;
        int pl_ = pos >> 10;
        int w   = pos & 1023;
        int row = w >> 3;
        int u   = (w & 7) * 8;
        const __half* src = (pl_ == 0) ? Qhb : Qlb;
        __half* dst = (pl_ == 0) ? qh : ql;
        *(uint4*)&dst[row * AKP + u] = *(const uint4*)(src + (size_t)(q0 + row) * DIM + u);
    }

    auto load_kv = [&](int st, int kvt) {
        const int kv0 = kvt * 64;
        __half* kvbase = smh + OKV0 + st * KVSTG;
        #pragma unroll
        for (int i = 0; i < 8; i++) {
            int uidx = tid + i * 256;
            int p    = uidx >> 9;
            int w    = uidx & 511;
            int row  = w >> 3;
            int u    = (w & 7) * 8;
            const __half* src;
            if (p == 0)      src = Khb;
            else if (p == 1) src = Klb;
            else if (p == 2) src = Vhb;
            else             src = Vlb;
            cp16h(&kvbase[p * 64 * AKP + row * AKP + u],
                  src + (size_t)(kv0 + row) * DIM + u);
        }
    };

    float o[8][4];
    float m[2], l[2];
    #pragma unroll
    for (int n = 0; n < 8; n++)
        #pragma unroll
        for (int e = 0; e < 4; e++)
            o[n][e] = 0.0f;
    m[0] = m[1] = -INFINITY;
    l[0] = l[1] = 0.0f;

    const int rb  = wid * 16;
    const int wq0 = q0 + rb;
    const int ntiles = 2 * qt + 2;

    load_kv(0, 0);
    cp_commit();
    __syncthreads();   // Q planes ready

    for (int kvt = 0; kvt < ntiles; kvt++) {
        const int st = kvt & 1;
        const int kv0 = kvt * 64;
        cp_wait<0>();
        __syncthreads();
        if (kvt + 1 < ntiles) { load_kv(st ^ 1, kvt + 1); cp_commit(); }

        const uint32_t kvb = sb + (uint32_t)(OKV0 + st * KVSTG) * 2u;
        const uint32_t khB = kvb;
        const uint32_t klB = kvb + (uint32_t)(64 * AKP) * 2u;
        const uint32_t vhB = kvb + (uint32_t)(2 * 64 * AKP) * 2u;
        const uint32_t vlB = kvb + (uint32_t)(3 * 64 * AKP) * 2u;

        const bool active = (kv0 <= wq0 + 15);
        if (active) {
            // ---- S = Q K^T ----
            float s[8][4];
            #pragma unroll
            for (int n = 0; n < 8; n++)
                #pragma unroll
                for (int e = 0; e < 4; e++)
                    s[n][e] = 0.0f;

            #pragma unroll
            for (int ks = 0; ks < 4; ks++) {
                const int kk = ks * 16;
                uint32_t aoff = (uint32_t)((rb + a_r) * AKP + kk + a_c) * 2u;
                uint32_t ahi[4], alo[4];
                ldmx4(ahi[0], ahi[1], ahi[2], ahi[3], sb + (uint32_t)(OQH * 2) + aoff);
                ldmx4(alo[0], alo[1], alo[2], alo[3], sb + (uint32_t)(OQL * 2) + aoff);
                uint32_t bh[8][2], bl[8][2];
                #pragma unroll
                for (int q = 0; q < 4; q++) {
                    uint32_t boff = (uint32_t)(((2 * q + b_rsel) * 8 + b_r) * AKP
                                               + kk + b_c) * 2u;
                    ldmx4(bh[2*q][0], bh[2*q][1], bh[2*q+1][0], bh[2*q+1][1], khB + boff);
                    ldmx4(bl[2*q][0], bl[2*q][1], bl[2*q+1][0], bl[2*q+1][1], klB + boff);
                }
                #pragma unroll
                for (int n = 0; n < 8; n++) {
                    mma16(s[n], ahi, bh[n]);
                    mma16(s[n], ahi, bl[n]);
                    mma16(s[n], alo, bh[n]);
                }
            }

            // ---- scale + causal mask ----
            const bool needmask = (kv0 + 63) > wq0;
            #pragma unroll
            for (int n = 0; n < 8; n++)
                #pragma unroll
                for (int e = 0; e < 4; e++) {
                    float v = s[n][e] * 0.125f;
                    if (needmask) {
                        int col = kv0 + n * 8 + 2 * t + (e & 1);
                        int row = wq0 + g + ((e >> 1) * 8);
                        if (col > row) v = -1e30f;
                    }
                    s[n][e] = v;
                }

            // ---- streaming softmax ----
            #pragma unroll
            for (int hh = 0; hh < 2; hh++) {
                float rowmax = -INFINITY;
                #pragma unroll
                for (int n = 0; n < 8; n++) {
                    rowmax = fmaxf(rowmax, s[n][hh * 2 + 0]);
                    rowmax = fmaxf(rowmax, s[n][hh * 2 + 1]);
                }
                rowmax = fmaxf(rowmax, __shfl_xor_sync(0xffffffffu, rowmax, 1));
                rowmax = fmaxf(rowmax, __shfl_xor_sync(0xffffffffu, rowmax, 2));
                float mnew = fmaxf(m[hh], rowmax);
                float alpha = __expf(m[hh] - mnew);
                m[hh] = mnew;
                float rs = 0.0f;
                #pragma unroll
                for (int n = 0; n < 8; n++) {
                    float p0 = __expf(s[n][hh * 2 + 0] - mnew);
                    float p1 = __expf(s[n][hh * 2 + 1] - mnew);
                    s[n][hh * 2 + 0] = p0;
                    s[n][hh * 2 + 1] = p1;
                    rs += p0 + p1;
                }
                rs += __shfl_xor_sync(0xffffffffu, rs, 1);
                rs += __shfl_xor_sync(0xffffffffu, rs, 2);
                l[hh] = l[hh] * alpha + rs;
                #pragma unroll
                for (int n = 0; n < 8; n++) {
                    o[n][hh * 2 + 0] *= alpha;
                    o[n][hh * 2 + 1] *= alpha;
                }
            }

            // ---- split P (x256) directly into A-fragments (registers, no smem) ----
            // C-frag (g,2t | g+8,2t) of n-block == A-frag regs for PV k-chunk ks=n/2:
            //   a0 = (g,  16ks+2t)   = ph01[2ks]
            //   a1 = (g+8,16ks+2t)   = ph23[2ks]
            //   a2 = (g,  16ks+8+2t) = ph01[2ks+1]
            //   a3 = (g+8,16ks+8+2t) = ph23[2ks+1]
            uint32_t ph01[8], ph23[8], pl01[8], pl23[8];
            #pragma unroll
            for (int n = 0; n < 8; n++) {
                __half h0, l0_, h1, l1_;
                splitf(s[n][0] * 256.0f, h0, l0_);
                splitf(s[n][1] * 256.0f, h1, l1_);
                ph01[n] = pack2(h0, h1);
                pl01[n] = pack2(l0_, l1_);
                splitf(s[n][2] * 256.0f, h0, l0_);
                splitf(s[n][3] * 256.0f, h1, l1_);
                ph23[n] = pack2(h0, h1);
                pl23[n] = pack2(l0_, l1_);
            }

            // ---- O += P V  (V transposed at read via ldmatrix.trans) ----
            const int rml = ((lane >> 3) & 1) * 8 + (lane & 7);
            const int cml0 = (lane >> 4) * 8;
            #pragma unroll
            for (int ks = 0; ks < 4; ks++) {
                const int kk = ks * 16;
                uint32_t ahi[4] = { ph01[2*ks], ph23[2*ks], ph01[2*ks+1], ph23[2*ks+1] };
                uint32_t alo[4] = { pl01[2*ks], pl23[2*ks], pl01[2*ks+1], pl23[2*ks+1] };
                #pragma unroll
                for (int nb = 0; nb < 4; nb++) {
                    uint32_t voff = (uint32_t)((kk + rml) * AKP + nb * 16 + cml0) * 2u;
                    uint32_t h0, h1, h2, h3, l0_, l1_, l2_, l3_;
                    ldmx4t(h0, h1, h2, h3, vhB + voff);
                    ldmx4t(l0_, l1_, l2_, l3_, vlB + voff);
                    uint32_t bh0[2] = { h0, h1 }, bh1[2] = { h2, h3 };
                    uint32_t bl0[2] = { l0_, l1_ }, bl1[2] = { l2_, l3_ };
                    mma16(o[2 * nb + 0], ahi, bh0);
                    mma16(o[2 * nb + 0], ahi, bl0);
                    mma16(o[2 * nb + 0], alo, bh0);
                    mma16(o[2 * nb + 1], ahi, bh1);
                    mma16(o[2 * nb + 1], ahi, bl1);
                    mma16(o[2 * nb + 1], alo, bh1);
                }
            }
        }
        __syncthreads();
    }

    // ---- epilogue: normalize (undo P x256), split, write O planes ----
    __half* Ohb = g_Oh + base;
    __half* Olb = g_Ol + base;
    {
        int r0 = q0 + rb + g;
        int r1 = r0 + 8;
        float inv0 = 1.0f / (256.0f * l[0]);
        float inv1 = 1.0f / (256.0f * l[1]);
        #pragma unroll
        for (int n = 0; n < 8; n++) {
            int c = n * 8 + 2 * t;
            __half h0, l0_, h1, l1_;
            splitf(o[n][0] * inv0, h0, l0_);
            splitf(o[n][1] * inv0, h1, l1_);
            *(__half2*)&Ohb[(size_t)r0 * DIM + c] = __halves2half2(h0, h1);
            *(__half2*)&Olb[(size_t)r0 * DIM + c] = __halves2half2(l0_, l1_);
            splitf(o[n][2] * inv1, h0, l0_);
            splitf(o[n][3] * inv1, h1, l1_);
            *(__half2*)&Ohb[(size_t)r1 * DIM + c] = __halves2half2(h0, h1);
            *(__half2*)&Olb[(size_t)r1 * DIM + c] = __halves2half2(l0_, l1_);
        }
    }
}

// ---------------- launch ----------------
extern "C" void kernel_launch(void* const* d_in, const int* in_sizes, int n_in,
                              void* d_out, int out_size)
{
    const float* x  = (const float*)d_in[0];
    const float* WQ = (const float*)d_in[1];
    const float* WK = (const float*)d_in[2];
    const float* WV = (const float*)d_in[3];
    const float* WO = (const float*)d_in[4];
    const int*  pos = (const int*)d_in[5];
    float* out = (float*)d_out;

    cudaFuncSetAttribute(gemm_h2<0>, cudaFuncAttributeMaxDynamicSharedMemorySize, GEMM_SMEM);
    cudaFuncSetAttribute(gemm_h2<1>, cudaFuncAttributeMaxDynamicSharedMemorySize, GEMM_SMEM);
    cudaFuncSetAttribute(gemm_h2<2>, cudaFuncAttributeMaxDynamicSharedMemorySize, GEMM_SMEM);
    cudaFuncSetAttribute(gemm_h2<3>, cudaFuncAttributeMaxDynamicSharedMemorySize, GEMM_SMEM);
    cudaFuncSetAttribute(attn_h2_kernel, cudaFuncAttributeMaxDynamicSharedMemorySize, ATT_SMEM);

    rope_table_kernel<<<(SEQ * 32 + 255) / 256, 256>>>(pos);
    convert_x_kernel<<<(NROWS * DIM / 4 + 255) / 256, 256>>>(x);
    convert_w_kernel<<<(DIM * DIM / 4 + 255) / 256, 256>>>(WQ, 0);
    convert_w_kernel<<<(DIM * DIM / 4 + 255) / 256, 256>>>(WK, 1);
    convert_w_kernel<<<(DIM * DIM / 4 + 255) / 256, 256>>>(WV, 2);
    convert_w_kernel<<<(DIM * DIM / 4 + 255) / 256, 256>>>(WO, 3);

    dim3 ggrid(DIM / 128, NROWS / 128);   // (8, 64)
    gemm_h2<0><<<ggrid, 256, GEMM_SMEM>>>(nullptr);
    gemm_h2<1><<<ggrid, 256, GEMM_SMEM>>>(nullptr);
    gemm_h2<2><<<ggrid, 256, GEMM_SMEM>>>(nullptr);

    attn_h2_kernel<<<dim3(SEQ / 128, BATCH * NHEAD), 256, ATT_SMEM>>>();

    gemm_h2<3><<<ggrid, 256, GEMM_SMEM>>>(out);
}

// round 9
// speedup vs baseline: 1.1676x; 1.0220x over previous
#include <cuda_runtime.h>
#include <cuda_fp16.h>
#include <math.h>
#include <stdint.h>

#define BATCH 4
#define SEQ   2048
#define DIM   1024
#define NHEAD 16
#define DH    64
#define NROWS (BATCH*SEQ)   // 8192

// ---------------- scratch (device globals) ----------------
__device__ __half g_Xh[(size_t)NROWS * DIM];
__device__ __half g_Xl[(size_t)NROWS * DIM];
__device__ __half g_Wh[(size_t)4 * DIM * DIM];
__device__ __half g_Wl[(size_t)4 * DIM * DIM];
__device__ __half g_Qh[(size_t)NROWS * DIM];
__device__ __half g_Ql[(size_t)NROWS * DIM];
__device__ __half g_Kh[(size_t)NROWS * DIM];
__device__ __half g_Kl[(size_t)NROWS * DIM];
__device__ __half g_Vh[(size_t)NROWS * DIM];
__device__ __half g_Vl[(size_t)NROWS * DIM];
__device__ __half g_Oh[(size_t)NROWS * DIM];
__device__ __half g_Ol[(size_t)NROWS * DIM];
__device__ float g_cos[SEQ * 32];
__device__ float g_sin[SEQ * 32];

// ---------------- helpers ----------------
__device__ __forceinline__ void splitf(float x, __half& h, __half& l) {
    h = __float2half_rn(x);
    l = __float2half_rn(x - __half2float(h));
}
__device__ __forceinline__ uint32_t pack2(__half a, __half b) {
    __half2 hh = __halves2half2(a, b);
    return *(uint32_t*)&hh;
}
__device__ __forceinline__ void mma16(float* c, const uint32_t* a, const uint32_t* b) {
    asm volatile(
        "mma.sync.aligned.m16n8k16.row.col.f32.f16.f16.f32 "
        "{%0,%1,%2,%3},{%4,%5,%6,%7},{%8,%9},{%0,%1,%2,%3};"
        : "+f"(c[0]), "+f"(c[1]), "+f"(c[2]), "+f"(c[3])
        : "r"(a[0]), "r"(a[1]), "r"(a[2]), "r"(a[3]), "r"(b[0]), "r"(b[1]));
}
__device__ __forceinline__ void ldmx4(uint32_t& d0, uint32_t& d1, uint32_t& d2, uint32_t& d3,
                                      uint32_t saddr) {
    asm volatile("ldmatrix.sync.aligned.m8n8.x4.shared.b16 {%0,%1,%2,%3}, [%4];"
                 : "=r"(d0), "=r"(d1), "=r"(d2), "=r"(d3) : "r"(saddr));
}
__device__ __forceinline__ void ldmx4t(uint32_t& d0, uint32_t& d1, uint32_t& d2, uint32_t& d3,
                                       uint32_t saddr) {
    asm volatile("ldmatrix.sync.aligned.m8n8.x4.trans.shared.b16 {%0,%1,%2,%3}, [%4];"
                 : "=r"(d0), "=r"(d1), "=r"(d2), "=r"(d3) : "r"(saddr));
}
__device__ __forceinline__ void cp16h(__half* dst, const __half* src) {
    unsigned s = (unsigned)__cvta_generic_to_shared(dst);
    asm volatile("cp.async.ca.shared.global [%0], [%1], 16;" :: "r"(s), "l"(src));
}
__device__ __forceinline__ void cp_commit() { asm volatile("cp.async.commit_group;"); }
template<int N>
__device__ __forceinline__ void cp_wait() { asm volatile("cp.async.wait_group %0;" :: "n"(N)); }

// ---------------- RoPE table ----------------
__global__ void rope_table_kernel(const int* __restrict__ pos)
{
    int idx = blockIdx.x * blockDim.x + threadIdx.x;
    if (idx >= SEQ * 32) return;
    int s = idx >> 5;
    int p = idx & 31;
    float inv = powf(10000.0f, -(float)(2 * p) / (float)DH);
    float ang = (float)pos[s] * inv;
    float sv, cv;
    sincosf(ang, &sv, &cv);
    g_cos[idx] = cv;
    g_sin[idx] = sv;
}

// ---------------- converters ----------------
__global__ void convert_x_kernel(const float* __restrict__ x)
{
    size_t i = ((size_t)blockIdx.x * blockDim.x + threadIdx.x) * 4;
    if (i >= (size_t)NROWS * DIM) return;
    float4 v = *(const float4*)(x + i);
    __half h0, l0, h1, l1, h2, l2, h3, l3;
    splitf(v.x, h0, l0); splitf(v.y, h1, l1);
    splitf(v.z, h2, l2); splitf(v.w, h3, l3);
    *(__half2*)&g_Xh[i]     = __halves2half2(h0, h1);
    *(__half2*)&g_Xh[i + 2] = __halves2half2(h2, h3);
    *(__half2*)&g_Xl[i]     = __halves2half2(l0, l1);
    *(__half2*)&g_Xl[i + 2] = __halves2half2(l2, l3);
}
// all 4 weights in one launch: blockIdx.y = widx
__global__ void convert_w_all_kernel(const float* __restrict__ W0,
                                     const float* __restrict__ W1,
                                     const float* __restrict__ W2,
                                     const float* __restrict__ W3)
{
    int widx = blockIdx.y;
    const float* W = (widx == 0) ? W0 : (widx == 1) ? W1 : (widx == 2) ? W2 : W3;
    size_t i = ((size_t)blockIdx.x * blockDim.x + threadIdx.x) * 4;
    if (i >= (size_t)DIM * DIM) return;
    size_t o = (size_t)widx * DIM * DIM + i;
    float4 v = *(const float4*)(W + i);
    v.x *= 256.0f; v.y *= 256.0f; v.z *= 256.0f; v.w *= 256.0f;
    __half h0, l0, h1, l1, h2, l2, h3, l3;
    splitf(v.x, h0, l0); splitf(v.y, h1, l1);
    splitf(v.z, h2, l2); splitf(v.w, h3, l3);
    *(__half2*)&g_Wh[o]     = __halves2half2(h0, h1);
    *(__half2*)&g_Wh[o + 2] = __halves2half2(h2, h3);
    *(__half2*)&g_Wl[o]     = __halves2half2(l0, l1);
    *(__half2*)&g_Wl[o + 2] = __halves2half2(l2, l3);
}

// ---------------- fp16x2 GEMM (unchanged from R8) ----------------
#define GKP 40
#define GPL (128 * GKP)
#define GSTG (4 * GPL)
#define GEMM_SMEM (2 * GSTG * 2)  // 81920 B

template<int MODE>
__global__ void __launch_bounds__(256, 2) gemm_h2(float* __restrict__ Cout)
{
    extern __shared__ __half smh[];
    const __half* Aph = (MODE == 3) ? g_Oh : g_Xh;
    const __half* Apl = (MODE == 3) ? g_Ol : g_Xl;
    const __half* Bph = g_Wh + (size_t)MODE * DIM * DIM;
    const __half* Bpl = g_Wl + (size_t)MODE * DIM * DIM;
    const uint32_t sb = (uint32_t)__cvta_generic_to_shared(smh);

    const int tid  = threadIdx.x;
    const int lane = tid & 31;
    const int wid  = tid >> 5;
    const int g    = lane >> 2;
    const int t    = lane & 3;
    const int wm   = wid & 1;
    const int wn   = wid >> 1;

    const int row0 = blockIdx.y * 128;
    const int col0 = blockIdx.x * 128;

    const int a_r = ((lane >> 3) & 1) * 8 + (lane & 7);
    const int a_c = ((lane >> 4) & 1) * 8;
    const int b_rsel = (lane >> 4);
    const int b_r = (lane & 7);
    const int b_c = ((lane >> 3) & 1) * 8;

    float acc[4][4][4];
    #pragma unroll
    for (int im = 0; im < 4; im++)
        #pragma unroll
        for (int in = 0; in < 4; in++)
            #pragma unroll
            for (int e = 0; e < 4; e++)
                acc[im][in][e] = 0.0f;

    auto load_stage = [&](int st, int kt) {
        const int k0 = kt * 32;
        #pragma unroll
        for (int i = 0; i < 8; i++) {
            int uidx = tid + i * 256;
            int p    = uidx >> 9;
            int w    = uidx & 511;
            int row  = w >> 2;
            int un   = (w & 3) * 8;
            const __half* src;
            if (p == 0)      src = Aph + (size_t)(row0 + row) * DIM + k0 + un;
            else if (p == 1) src = Apl + (size_t)(row0 + row) * DIM + k0 + un;
            else if (p == 2) src = Bph + (size_t)(col0 + row) * DIM + k0 + un;
            else             src = Bpl + (size_t)(col0 + row) * DIM + k0 + un;
            cp16h(&smh[st * GSTG + p * GPL + row * GKP + un], src);
        }
    };

    load_stage(0, 0);
    cp_commit();

    const int NKT = DIM / 32;
    for (int kt = 0; kt < NKT; kt++) {
        const int st = kt & 1;
        cp_wait<0>();
        __syncthreads();
        if (kt + 1 < NKT) { load_stage(st ^ 1, kt + 1); cp_commit(); }

        const uint32_t s0 = sb + (uint32_t)(st * GSTG) * 2u;
        #pragma unroll
        for (int kq = 0; kq < 2; kq++) {
            const int kk = kq * 16;
            uint32_t bh[4][2], bl[4][2];
            #pragma unroll
            for (int q = 0; q < 2; q++) {
                uint32_t boff = (uint32_t)((wn * 32 + (2 * q + b_rsel) * 8 + b_r) * GKP
                                           + kk + b_c) * 2u;
                ldmx4(bh[2*q][0], bh[2*q][1], bh[2*q+1][0], bh[2*q+1][1],
                      s0 + (uint32_t)(2 * GPL) * 2u + boff);
                ldmx4(bl[2*q][0], bl[2*q][1], bl[2*q+1][0], bl[2*q+1][1],
                      s0 + (uint32_t)(3 * GPL) * 2u + boff);
            }
            #pragma unroll
            for (int im = 0; im < 4; im++) {
                uint32_t aoff = (uint32_t)((wm * 64 + im * 16 + a_r) * GKP + kk + a_c) * 2u;
                uint32_t ahi[4], alo[4];
                ldmx4(ahi[0], ahi[1], ahi[2], ahi[3], s0 + aoff);
                ldmx4(alo[0], alo[1], alo[2], alo[3], s0 + (uint32_t)GPL * 2u + aoff);
                #pragma unroll
                for (int in = 0; in < 4; in++) {
                    mma16(acc[im][in], ahi, bh[in]);
                    mma16(acc[im][in], ahi, bl[in]);
                    mma16(acc[im][in], alo, bh[in]);
                }
            }
        }
        __syncthreads();
    }

    const float sc = 1.0f / 256.0f;
    #pragma unroll
    for (int im = 0; im < 4; im++) {
        int r0 = row0 + wm * 64 + im * 16 + g;
        int r1 = r0 + 8;
        #pragma unroll
        for (int in = 0; in < 4; in++) {
            int c = col0 + wn * 32 + in * 8 + 2 * t;
            float v0 = acc[im][in][0] * sc, v1 = acc[im][in][1] * sc;
            float v2 = acc[im][in][2] * sc, v3 = acc[im][in][3] * sc;
            if (MODE == 3) {
                float2 o0 = { v0, v1 };
                float2 o1 = { v2, v3 };
                *(float2*)(Cout + (size_t)r0 * DIM + c) = o0;
                *(float2*)(Cout + (size_t)r1 * DIM + c) = o1;
            } else {
                if (MODE <= 1) {
                    int p = (c & 63) >> 1;
                    int s0i = r0 & (SEQ - 1);
                    int s1i = r1 & (SEQ - 1);
                    float cv0 = g_cos[s0i * 32 + p], sv0 = g_sin[s0i * 32 + p];
                    float cv1 = g_cos[s1i * 32 + p], sv1 = g_sin[s1i * 32 + p];
                    float n0 = v0 * cv0 - v1 * sv0, n1 = v0 * sv0 + v1 * cv0;
                    float n2 = v2 * cv1 - v3 * sv1, n3 = v2 * sv1 + v3 * cv1;
                    v0 = n0; v1 = n1; v2 = n2; v3 = n3;
                }
                __half* Ch = (MODE == 0) ? g_Qh : (MODE == 1) ? g_Kh : g_Vh;
                __half* Cl = (MODE == 0) ? g_Ql : (MODE == 1) ? g_Kl : g_Vl;
                __half h0, l0, h1, l1;
                splitf(v0, h0, l0); splitf(v1, h1, l1);
                *(__half2*)&Ch[(size_t)r0 * DIM + c] = __halves2half2(h0, h1);
                *(__half2*)&Cl[(size_t)r0 * DIM + c] = __halves2half2(l0, l1);
                splitf(v2, h0, l0); splitf(v3, h1, l1);
                *(__half2*)&Ch[(size_t)r1 * DIM + c] = __halves2half2(h0, h1);
                *(__half2*)&Cl[(size_t)r1 * DIM + c] = __halves2half2(l0, l1);
            }
        }
    }
}

// ---------------- flash attention: 4 warps x 32 q-rows (im=2), 2 CTAs/SM ----------------
#define AKP 72
#define OQH 0
#define OQL (128 * AKP)                       // 9216
#define OKV0 (2 * 128 * AKP)                  // 18432
#define KVSTG (4 * 64 * AKP)                  // 18432 halves per stage
#define ATT_SMEM ((OKV0 + 2 * KVSTG) * 2)     // 110592 B

__global__ void __launch_bounds__(128, 2) attn_h2_kernel()
{
    extern __shared__ __half smh[];
    __half* qh = smh + OQH;  __half* ql = smh + OQL;
    const uint32_t sb = (uint32_t)__cvta_generic_to_shared(smh);

    const int tid  = threadIdx.x;
    const int lane = tid & 31;
    const int wid  = tid >> 5;   // 0..3
    const int g    = lane >> 2;
    const int t    = lane & 3;

    const int qt = (int)gridDim.x - 1 - (int)blockIdx.x;  // heavy tiles first
    const int q0 = qt * 128;
    const int bh_ = blockIdx.y;
    const int b  = bh_ >> 4;
    const int h  = bh_ & 15;

    const size_t base = (size_t)b * SEQ * DIM + h * DH;
    const __half* Qhb = g_Qh + base;  const __half* Qlb = g_Ql + base;
    const __half* Khb = g_Kh + base;  const __half* Klb = g_Kl + base;
    const __half* Vhb = g_Vh + base;  const __half* Vlb = g_Vl + base;

    const int a_r = ((lane >> 3) & 1) * 8 + (lane & 7);
    const int a_c = ((lane >> 4) & 1) * 8;
    const int b_rsel = (lane >> 4);
    const int b_r = (lane & 7);
    const int b_c = ((lane >> 3) & 1) * 8;

    // load Q planes (128 x 64 halves each): 2048 16B units / 128 thr = 16
    #pragma unroll
    for (int i = 0; i < 16; i++) {
        int pos = tid + i * 128;
        int pl_ = pos >> 10;
        int w   = pos & 1023;
        int row = w >> 3;
        int u   = (w & 7) * 8;
        const __half* src = (pl_ == 0) ? Qhb : Qlb;
        __half* dst = (pl_ == 0) ? qh : ql;
        *(uint4*)&dst[row * AKP + u] = *(const uint4*)(src + (size_t)(q0 + row) * DIM + u);
    }

    auto load_kv = [&](int st, int kvt) {
        const int kv0 = kvt * 64;
        __half* kvbase = smh + OKV0 + st * KVSTG;
        #pragma unroll
        for (int i = 0; i < 16; i++) {
            int uidx = tid + i * 128;
            int p    = uidx >> 9;
            int w    = uidx & 511;
            int row  = w >> 3;
            int u    = (w & 7) * 8;
            const __half* src;
            if (p == 0)      src = Khb;
            else if (p == 1) src = Klb;
            else if (p == 2) src = Vhb;
            else             src = Vlb;
            cp16h(&kvbase[p * 64 * AKP + row * AKP + u],
                  src + (size_t)(kv0 + row) * DIM + u);
        }
    };

    float o[2][8][4];
    float m[4], l[4];
    #pragma unroll
    for (int im = 0; im < 2; im++)
        #pragma unroll
        for (int n = 0; n < 8; n++)
            #pragma unroll
            for (int e = 0; e < 4; e++)
                o[im][n][e] = 0.0f;
    #pragma unroll
    for (int i = 0; i < 4; i++) { m[i] = -INFINITY; l[i] = 0.0f; }

    const int rb  = wid * 32;          // warp's 32 q-rows within tile
    const int wq0 = q0 + rb;
    const int ntiles = 2 * qt + 2;

    load_kv(0, 0);
    cp_commit();
    __syncthreads();   // Q planes ready

    for (int kvt = 0; kvt < ntiles; kvt++) {
        const int st = kvt & 1;
        const int kv0 = kvt * 64;
        cp_wait<0>();
        __syncthreads();
        if (kvt + 1 < ntiles) { load_kv(st ^ 1, kvt + 1); cp_commit(); }

        const uint32_t kvb = sb + (uint32_t)(OKV0 + st * KVSTG) * 2u;
        const uint32_t khB = kvb;
        const uint32_t klB = kvb + (uint32_t)(64 * AKP) * 2u;
        const uint32_t vhB = kvb + (uint32_t)(2 * 64 * AKP) * 2u;
        const uint32_t vlB = kvb + (uint32_t)(3 * 64 * AKP) * 2u;

        const bool active = (kv0 <= wq0 + 31);
        if (active) {
            // ---- S = Q K^T  (im=2: 32 q-rows per warp) ----
            float s[2][8][4];
            #pragma unroll
            for (int im = 0; im < 2; im++)
                #pragma unroll
                for (int n = 0; n < 8; n++)
                    #pragma unroll
                    for (int e = 0; e < 4; e++)
                        s[im][n][e] = 0.0f;

            #pragma unroll
            for (int ks = 0; ks < 4; ks++) {
                const int kk = ks * 16;
                uint32_t ahi[2][4], alo[2][4];
                #pragma unroll
                for (int im = 0; im < 2; im++) {
                    uint32_t aoff = (uint32_t)((rb + im * 16 + a_r) * AKP + kk + a_c) * 2u;
                    ldmx4(ahi[im][0], ahi[im][1], ahi[im][2], ahi[im][3],
                          sb + (uint32_t)(OQH * 2) + aoff);
                    ldmx4(alo[im][0], alo[im][1], alo[im][2], alo[im][3],
                          sb + (uint32_t)(OQL * 2) + aoff);
                }
                uint32_t bh[8][2], bl[8][2];
                #pragma unroll
                for (int q = 0; q < 4; q++) {
                    uint32_t boff = (uint32_t)(((2 * q + b_rsel) * 8 + b_r) * AKP
                                               + kk + b_c) * 2u;
                    ldmx4(bh[2*q][0], bh[2*q][1], bh[2*q+1][0], bh[2*q+1][1], khB + boff);
                    ldmx4(bl[2*q][0], bl[2*q][1], bl[2*q+1][0], bl[2*q+1][1], klB + boff);
                }
                #pragma unroll
                for (int im = 0; im < 2; im++)
                    #pragma unroll
                    for (int n = 0; n < 8; n++) {
                        mma16(s[im][n], ahi[im], bh[n]);
                        mma16(s[im][n], ahi[im], bl[n]);
                        mma16(s[im][n], alo[im], bh[n]);
                    }
            }

            // ---- scale + causal mask ----
            const bool needmask = (kv0 + 63) > wq0;
            #pragma unroll
            for (int im = 0; im < 2; im++)
                #pragma unroll
                for (int n = 0; n < 8; n++)
                    #pragma unroll
                    for (int e = 0; e < 4; e++) {
                        float v = s[im][n][e] * 0.125f;
                        if (needmask) {
                            int col = kv0 + n * 8 + 2 * t + (e & 1);
                            int row = wq0 + im * 16 + g + ((e >> 1) * 8);
                            if (col > row) v = -1e30f;
                        }
                        s[im][n][e] = v;
                    }

            // ---- streaming softmax (4 row groups: im*2+hh) ----
            #pragma unroll
            for (int im = 0; im < 2; im++) {
                #pragma unroll
                for (int hh = 0; hh < 2; hh++) {
                    int ri = im * 2 + hh;
                    float rowmax = -INFINITY;
                    #pragma unroll
                    for (int n = 0; n < 8; n++) {
                        rowmax = fmaxf(rowmax, s[im][n][hh * 2 + 0]);
                        rowmax = fmaxf(rowmax, s[im][n][hh * 2 + 1]);
                    }
                    rowmax = fmaxf(rowmax, __shfl_xor_sync(0xffffffffu, rowmax, 1));
                    rowmax = fmaxf(rowmax, __shfl_xor_sync(0xffffffffu, rowmax, 2));
                    float mnew = fmaxf(m[ri], rowmax);
                    float alpha = __expf(m[ri] - mnew);
                    m[ri] = mnew;
                    float rs = 0.0f;
                    #pragma unroll
                    for (int n = 0; n < 8; n++) {
                        float p0 = __expf(s[im][n][hh * 2 + 0] - mnew);
                        float p1 = __expf(s[im][n][hh * 2 + 1] - mnew);
                        s[im][n][hh * 2 + 0] = p0;
                        s[im][n][hh * 2 + 1] = p1;
                        rs += p0 + p1;
                    }
                    rs += __shfl_xor_sync(0xffffffffu, rs, 1);
                    rs += __shfl_xor_sync(0xffffffffu, rs, 2);
                    l[ri] = l[ri] * alpha + rs;
                    #pragma unroll
                    for (int n = 0; n < 8; n++) {
                        o[im][n][hh * 2 + 0] *= alpha;
                        o[im][n][hh * 2 + 1] *= alpha;
                    }
                }
            }

            // ---- O += P V : split P per-ks (transient regs), V via ldmatrix.trans ----
            const int rml = ((lane >> 3) & 1) * 8 + (lane & 7);
            const int cml0 = (lane >> 4) * 8;
            #pragma unroll
            for (int ks = 0; ks < 4; ks++) {
                const int kk = ks * 16;
                // A-frags from S C-frags: n-blocks 2ks, 2ks+1
                uint32_t ahi[2][4], alo[2][4];
                #pragma unroll
                for (int im = 0; im < 2; im++) {
                    __half h0, l0_, h1, l1_;
                    splitf(s[im][2*ks][0] * 256.0f, h0, l0_);
                    splitf(s[im][2*ks][1] * 256.0f, h1, l1_);
                    ahi[im][0] = pack2(h0, h1);  alo[im][0] = pack2(l0_, l1_);
                    splitf(s[im][2*ks][2] * 256.0f, h0, l0_);
                    splitf(s[im][2*ks][3] * 256.0f, h1, l1_);
                    ahi[im][1] = pack2(h0, h1);  alo[im][1] = pack2(l0_, l1_);
                    splitf(s[im][2*ks+1][0] * 256.0f, h0, l0_);
                    splitf(s[im][2*ks+1][1] * 256.0f, h1, l1_);
                    ahi[im][2] = pack2(h0, h1);  alo[im][2] = pack2(l0_, l1_);
                    splitf(s[im][2*ks+1][2] * 256.0f, h0, l0_);
                    splitf(s[im][2*ks+1][3] * 256.0f, h1, l1_);
                    ahi[im][3] = pack2(h0, h1);  alo[im][3] = pack2(l0_, l1_);
                }
                #pragma unroll
                for (int nb = 0; nb < 4; nb++) {
                    uint32_t voff = (uint32_t)((kk + rml) * AKP + nb * 16 + cml0) * 2u;
                    uint32_t h0, h1, h2, h3, l0_, l1_, l2_, l3_;
                    ldmx4t(h0, h1, h2, h3, vhB + voff);
                    ldmx4t(l0_, l1_, l2_, l3_, vlB + voff);
                    uint32_t bh0[2] = { h0, h1 }, bh1[2] = { h2, h3 };
                    uint32_t bl0[2] = { l0_, l1_ }, bl1[2] = { l2_, l3_ };
                    #pragma unroll
                    for (int im = 0; im < 2; im++) {
                        mma16(o[im][2 * nb + 0], ahi[im], bh0);
                        mma16(o[im][2 * nb + 0], ahi[im], bl0);
                        mma16(o[im][2 * nb + 0], alo[im], bh0);
                        mma16(o[im][2 * nb + 1], ahi[im], bh1);
                        mma16(o[im][2 * nb + 1], ahi[im], bl1);
                        mma16(o[im][2 * nb + 1], alo[im], bh1);
                    }
                }
            }
        }
        __syncthreads();
    }

    // ---- epilogue: normalize (undo P x256), split, write O planes ----
    __half* Ohb = g_Oh + base;
    __half* Olb = g_Ol + base;
    #pragma unroll
    for (int im = 0; im < 2; im++) {
        int r0 = q0 + rb + im * 16 + g;
        int r1 = r0 + 8;
        float inv0 = 1.0f / (256.0f * l[im * 2 + 0]);
        float inv1 = 1.0f / (256.0f * l[im * 2 + 1]);
        #pragma unroll
        for (int n = 0; n < 8; n++) {
            int c = n * 8 + 2 * t;
            __half h0, l0_, h1, l1_;
            splitf(o[im][n][0] * inv0, h0, l0_);
            splitf(o[im][n][1] * inv0, h1, l1_);
            *(__half2*)&Ohb[(size_t)r0 * DIM + c] = __halves2half2(h0, h1);
            *(__half2*)&Olb[(size_t)r0 * DIM + c] = __halves2half2(l0_, l1_);
            splitf(o[im][n][2] * inv1, h0, l0_);
            splitf(o[im][n][3] * inv1, h1, l1_);
            *(__half2*)&Ohb[(size_t)r1 * DIM + c] = __halves2half2(h0, h1);
            *(__half2*)&Olb[(size_t)r1 * DIM + c] = __halves2half2(l0_, l1_);
        }
    }
}

// ---------------- launch ----------------
extern "C" void kernel_launch(void* const* d_in, const int* in_sizes, int n_in,
                              void* d_out, int out_size)
{
    const float* x  = (const float*)d_in[0];
    const float* WQ = (const float*)d_in[1];
    const float* WK = (const float*)d_in[2];
    const float* WV = (const float*)d_in[3];
    const float* WO = (const float*)d_in[4];
    const int*  pos = (const int*)d_in[5];
    float* out = (float*)d_out;

    cudaFuncSetAttribute(gemm_h2<0>, cudaFuncAttributeMaxDynamicSharedMemorySize, GEMM_SMEM);
    cudaFuncSetAttribute(gemm_h2<1>, cudaFuncAttributeMaxDynamicSharedMemorySize, GEMM_SMEM);
    cudaFuncSetAttribute(gemm_h2<2>, cudaFuncAttributeMaxDynamicSharedMemorySize, GEMM_SMEM);
    cudaFuncSetAttribute(gemm_h2<3>, cudaFuncAttributeMaxDynamicSharedMemorySize, GEMM_SMEM);
    cudaFuncSetAttribute(attn_h2_kernel, cudaFuncAttributeMaxDynamicSharedMemorySize, ATT_SMEM);

    rope_table_kernel<<<(SEQ * 32 + 255) / 256, 256>>>(pos);
    convert_x_kernel<<<(NROWS * DIM / 4 + 255) / 256, 256>>>(x);
    convert_w_all_kernel<<<dim3((DIM * DIM / 4 + 255) / 256, 4), 256>>>(WQ, WK, WV, WO);

    dim3 ggrid(DIM / 128, NROWS / 128);   // (8, 64)
    gemm_h2<0><<<ggrid, 256, GEMM_SMEM>>>(nullptr);
    gemm_h2<1><<<ggrid, 256, GEMM_SMEM>>>(nullptr);
    gemm_h2<2><<<ggrid, 256, GEMM_SMEM>>>(nullptr);

    attn_h2_kernel<<<dim3(SEQ / 128, BATCH * NHEAD), 128, ATT_SMEM>>>();

    gemm_h2<3><<<ggrid, 256, GEMM_SMEM>>>(out);
}

// round 10
// speedup vs baseline: 1.2333x; 1.0562x over previous
#include <cuda_runtime.h>
#include <cuda_fp16.h>
#include <math.h>
#include <stdint.h>

#define BATCH 4
#define SEQ   2048
#define DIM   1024
#define NHEAD 16
#define DH    64
#define NROWS (BATCH*SEQ)   // 8192

// ---------------- scratch (device globals) ----------------
__device__ __half g_Xh[(size_t)NROWS * DIM];
__device__ __half g_Xl[(size_t)NROWS * DIM];
__device__ __half g_Wh[(size_t)4 * DIM * DIM];
__device__ __half g_Wl[(size_t)4 * DIM * DIM];
__device__ __half g_Qh[(size_t)NROWS * DIM];
__device__ __half g_Ql[(size_t)NROWS * DIM];
__device__ __half g_Kh[(size_t)NROWS * DIM];
__device__ __half g_Kl[(size_t)NROWS * DIM];
__device__ __half g_Vh[(size_t)NROWS * DIM];
__device__ __half g_Vl[(size_t)NROWS * DIM];
__device__ __half g_Oh[(size_t)NROWS * DIM];
__device__ __half g_Ol[(size_t)NROWS * DIM];
__device__ float g_cos[SEQ * 32];
__device__ float g_sin[SEQ * 32];

// ---------------- helpers ----------------
__device__ __forceinline__ void splitf(float x, __half& h, __half& l) {
    h = __float2half_rn(x);
    l = __float2half_rn(x - __half2float(h));
}
__device__ __forceinline__ uint32_t pack2(__half a, __half b) {
    __half2 hh = __halves2half2(a, b);
    return *(uint32_t*)&hh;
}
__device__ __forceinline__ void mma16(float* c, const uint32_t* a, const uint32_t* b) {
    asm volatile(
        "mma.sync.aligned.m16n8k16.row.col.f32.f16.f16.f32 "
        "{%0,%1,%2,%3},{%4,%5,%6,%7},{%8,%9},{%0,%1,%2,%3};"
        : "+f"(c[0]), "+f"(c[1]), "+f"(c[2]), "+f"(c[3])
        : "r"(a[0]), "r"(a[1]), "r"(a[2]), "r"(a[3]), "r"(b[0]), "r"(b[1]));
}
__device__ __forceinline__ void ldmx4(uint32_t& d0, uint32_t& d1, uint32_t& d2, uint32_t& d3,
                                      uint32_t saddr) {
    asm volatile("ldmatrix.sync.aligned.m8n8.x4.shared.b16 {%0,%1,%2,%3}, [%4];"
                 : "=r"(d0), "=r"(d1), "=r"(d2), "=r"(d3) : "r"(saddr));
}
__device__ __forceinline__ void ldmx4t(uint32_t& d0, uint32_t& d1, uint32_t& d2, uint32_t& d3,
                                       uint32_t saddr) {
    asm volatile("ldmatrix.sync.aligned.m8n8.x4.trans.shared.b16 {%0,%1,%2,%3}, [%4];"
                 : "=r"(d0), "=r"(d1), "=r"(d2), "=r"(d3) : "r"(saddr));
}
__device__ __forceinline__ void cp16h(__half* dst, const __half* src) {
    unsigned s = (unsigned)__cvta_generic_to_shared(dst);
    asm volatile("cp.async.ca.shared.global [%0], [%1], 16;" :: "r"(s), "l"(src));
}
__device__ __forceinline__ void cp_commit() { asm volatile("cp.async.commit_group;"); }
template<int N>
__device__ __forceinline__ void cp_wait() { asm volatile("cp.async.wait_group %0;" :: "n"(N)); }

// ---------------- RoPE table ----------------
__global__ void rope_table_kernel(const int* __restrict__ pos)
{
    int idx = blockIdx.x * blockDim.x + threadIdx.x;
    if (idx >= SEQ * 32) return;
    int s = idx >> 5;
    int p = idx & 31;
    float inv = powf(10000.0f, -(float)(2 * p) / (float)DH);
    float ang = (float)pos[s] * inv;
    float sv, cv;
    sincosf(ang, &sv, &cv);
    g_cos[idx] = cv;
    g_sin[idx] = sv;
}

// ---------------- converters ----------------
__global__ void convert_x_kernel(const float* __restrict__ x)
{
    size_t i = ((size_t)blockIdx.x * blockDim.x + threadIdx.x) * 4;
    if (i >= (size_t)NROWS * DIM) return;
    float4 v = *(const float4*)(x + i);
    __half h0, l0, h1, l1, h2, l2, h3, l3;
    splitf(v.x, h0, l0); splitf(v.y, h1, l1);
    splitf(v.z, h2, l2); splitf(v.w, h3, l3);
    *(__half2*)&g_Xh[i]     = __halves2half2(h0, h1);
    *(__half2*)&g_Xh[i + 2] = __halves2half2(h2, h3);
    *(__half2*)&g_Xl[i]     = __halves2half2(l0, l1);
    *(__half2*)&g_Xl[i + 2] = __halves2half2(l2, l3);
}
__global__ void convert_w_all_kernel(const float* __restrict__ W0,
                                     const float* __restrict__ W1,
                                     const float* __restrict__ W2,
                                     const float* __restrict__ W3)
{
    int widx = blockIdx.y;
    const float* W = (widx == 0) ? W0 : (widx == 1) ? W1 : (widx == 2) ? W2 : W3;
    size_t i = ((size_t)blockIdx.x * blockDim.x + threadIdx.x) * 4;
    if (i >= (size_t)DIM * DIM) return;
    size_t o = (size_t)widx * DIM * DIM + i;
    float4 v = *(const float4*)(W + i);
    v.x *= 256.0f; v.y *= 256.0f; v.z *= 256.0f; v.w *= 256.0f;
    __half h0, l0, h1, l1, h2, l2, h3, l3;
    splitf(v.x, h0, l0); splitf(v.y, h1, l1);
    splitf(v.z, h2, l2); splitf(v.w, h3, l3);
    *(__half2*)&g_Wh[o]     = __halves2half2(h0, h1);
    *(__half2*)&g_Wh[o + 2] = __halves2half2(h2, h3);
    *(__half2*)&g_Wl[o]     = __halves2half2(l0, l1);
    *(__half2*)&g_Wl[o + 2] = __halves2half2(l2, l3);
}

// ---------------- fp16x2 GEMM: 4 warps x (64x64) tiles, CTA 128x128 ----------------
// FUSED: blockIdx.z = mode (0=Q rope,1=K rope,2=V); !FUSED: mode 3, out-proj -> Cout
#define GKP 40
#define GPL (128 * GKP)
#define GSTG (4 * GPL)
#define GEMM_SMEM (2 * GSTG * 2)  // 81920 B

template<bool FUSED>
__global__ void __launch_bounds__(128, 2) gemm_h2(float* __restrict__ Cout)
{
    extern __shared__ __half smh[];
    const int mode = FUSED ? (int)blockIdx.z : 3;
    const __half* Aph = FUSED ? g_Xh : g_Oh;
    const __half* Apl = FUSED ? g_Xl : g_Ol;
    const __half* Bph = g_Wh + (size_t)mode * DIM * DIM;
    const __half* Bpl = g_Wl + (size_t)mode * DIM * DIM;
    const uint32_t sb = (uint32_t)__cvta_generic_to_shared(smh);

    const int tid  = threadIdx.x;
    const int lane = tid & 31;
    const int wid  = tid >> 5;    // 0..3
    const int g    = lane >> 2;
    const int t    = lane & 3;
    const int wm   = wid & 1;     // 64-row half
    const int wn   = wid >> 1;    // 64-col half

    const int row0 = blockIdx.y * 128;
    const int col0 = blockIdx.x * 128;

    const int a_r = ((lane >> 3) & 1) * 8 + (lane & 7);
    const int a_c = ((lane >> 4) & 1) * 8;
    const int b_rsel = (lane >> 4);
    const int b_r = (lane & 7);
    const int b_c = ((lane >> 3) & 1) * 8;

    float acc[4][8][4];
    #pragma unroll
    for (int im = 0; im < 4; im++)
        #pragma unroll
        for (int in = 0; in < 8; in++)
            #pragma unroll
            for (int e = 0; e < 4; e++)
                acc[im][in][e] = 0.0f;

    // stage loader: 4 planes x 128 rows x 4 16B-units = 2048 units / 128 thr = 16 each
    auto load_stage = [&](int st, int kt) {
        const int k0 = kt * 32;
        #pragma unroll
        for (int i = 0; i < 16; i++) {
            int uidx = tid + i * 128;
            int p    = uidx >> 9;
            int w    = uidx & 511;
            int row  = w >> 2;
            int un   = (w & 3) * 8;
            const __half* src;
            if (p == 0)      src = Aph + (size_t)(row0 + row) * DIM + k0 + un;
            else if (p == 1) src = Apl + (size_t)(row0 + row) * DIM + k0 + un;
            else if (p == 2) src = Bph + (size_t)(col0 + row) * DIM + k0 + un;
            else             src = Bpl + (size_t)(col0 + row) * DIM + k0 + un;
            cp16h(&smh[st * GSTG + p * GPL + row * GKP + un], src);
        }
    };

    load_stage(0, 0);
    cp_commit();

    const int NKT = DIM / 32;
    for (int kt = 0; kt < NKT; kt++) {
        const int st = kt & 1;
        cp_wait<0>();
        __syncthreads();
        if (kt + 1 < NKT) { load_stage(st ^ 1, kt + 1); cp_commit(); }

        const uint32_t s0 = sb + (uint32_t)(st * GSTG) * 2u;
        #pragma unroll
        for (int kq = 0; kq < 2; kq++) {
            const int kk = kq * 16;
            // B fragments: 8 n-blocks (4 ldmx4 pairs) x 2 planes
            uint32_t bh[8][2], bl[8][2];
            #pragma unroll
            for (int q = 0; q < 4; q++) {
                uint32_t boff = (uint32_t)((wn * 64 + (2 * q + b_rsel) * 8 + b_r) * GKP
                                           + kk + b_c) * 2u;
                ldmx4(bh[2*q][0], bh[2*q][1], bh[2*q+1][0], bh[2*q+1][1],
                      s0 + (uint32_t)(2 * GPL) * 2u + boff);
                ldmx4(bl[2*q][0], bl[2*q][1], bl[2*q+1][0], bl[2*q+1][1],
                      s0 + (uint32_t)(3 * GPL) * 2u + boff);
            }
            #pragma unroll
            for (int im = 0; im < 4; im++) {
                uint32_t aoff = (uint32_t)((wm * 64 + im * 16 + a_r) * GKP + kk + a_c) * 2u;
                uint32_t ahi[4], alo[4];
                ldmx4(ahi[0], ahi[1], ahi[2], ahi[3], s0 + aoff);
                ldmx4(alo[0], alo[1], alo[2], alo[3], s0 + (uint32_t)GPL * 2u + aoff);
                #pragma unroll
                for (int in = 0; in < 8; in++) {
                    mma16(acc[im][in], ahi, bh[in]);
                    mma16(acc[im][in], ahi, bl[in]);
                    mma16(acc[im][in], alo, bh[in]);
                }
            }
        }
        __syncthreads();
    }

    const float sc = 1.0f / 256.0f;
    #pragma unroll
    for (int im = 0; im < 4; im++) {
        int r0 = row0 + wm * 64 + im * 16 + g;
        int r1 = r0 + 8;
        #pragma unroll
        for (int in = 0; in < 8; in++) {
            int c = col0 + wn * 64 + in * 8 + 2 * t;
            float v0 = acc[im][in][0] * sc, v1 = acc[im][in][1] * sc;
            float v2 = acc[im][in][2] * sc, v3 = acc[im][in][3] * sc;
            if (!FUSED) {
                float2 o0 = { v0, v1 };
                float2 o1 = { v2, v3 };
                *(float2*)(Cout + (size_t)r0 * DIM + c) = o0;
                *(float2*)(Cout + (size_t)r1 * DIM + c) = o1;
            } else {
                if (mode <= 1) {
                    int p = (c & 63) >> 1;
                    int s0i = r0 & (SEQ - 1);
                    int s1i = r1 & (SEQ - 1);
                    float cv0 = g_cos[s0i * 32 + p], sv0 = g_sin[s0i * 32 + p];
                    float cv1 = g_cos[s1i * 32 + p], sv1 = g_sin[s1i * 32 + p];
                    float n0 = v0 * cv0 - v1 * sv0, n1 = v0 * sv0 + v1 * cv0;
                    float n2 = v2 * cv1 - v3 * sv1, n3 = v2 * sv1 + v3 * cv1;
                    v0 = n0; v1 = n1; v2 = n2; v3 = n3;
                }
                __half* Ch = (mode == 0) ? g_Qh : (mode == 1) ? g_Kh : g_Vh;
                __half* Cl = (mode == 0) ? g_Ql : (mode == 1) ? g_Kl : g_Vl;
                __half h0, l0, h1, l1;
                splitf(v0, h0, l0); splitf(v1, h1, l1);
                *(__half2*)&Ch[(size_t)r0 * DIM + c] = __halves2half2(h0, h1);
                *(__half2*)&Cl[(size_t)r0 * DIM + c] = __halves2half2(l0, l1);
                splitf(v2, h0, l0); splitf(v3, h1, l1);
                *(__half2*)&Ch[(size_t)r1 * DIM + c] = __halves2half2(h0, h1);
                *(__half2*)&Cl[(size_t)r1 * DIM + c] = __halves2half2(l0, l1);
            }
        }
    }
}

// ---------------- flash attention: 4 warps x 32 q-rows, 2 CTAs/SM (R9, unchanged) ----------------
#define AKP 72
#define OQH 0
#define OQL (128 * AKP)
#define OKV0 (2 * 128 * AKP)
#define KVSTG (4 * 64 * AKP)
#define ATT_SMEM ((OKV0 + 2 * KVSTG) * 2)     // 110592 B

__global__ void __launch_bounds__(128, 2) attn_h2_kernel()
{
    extern __shared__ __half smh[];
    __half* qh = smh + OQH;  __half* ql = smh + OQL;
    const uint32_t sb = (uint32_t)__cvta_generic_to_shared(smh);

    const int tid  = threadIdx.x;
    const int lane = tid & 31;
    const int wid  = tid >> 5;
    const int g    = lane >> 2;
    const int t    = lane & 3;

    const int qt = (int)gridDim.x - 1 - (int)blockIdx.x;
    const int q0 = qt * 128;
    const int bh_ = blockIdx.y;
    const int b  = bh_ >> 4;
    const int h  = bh_ & 15;

    const size_t base = (size_t)b * SEQ * DIM + h * DH;
    const __half* Qhb = g_Qh + base;  const __half* Qlb = g_Ql + base;
    const __half* Khb = g_Kh + base;  const __half* Klb = g_Kl + base;
    const __half* Vhb = g_Vh + base;  const __half* Vlb = g_Vl + base;

    const int a_r = ((lane >> 3) & 1) * 8 + (lane & 7);
    const int a_c = ((lane >> 4) & 1) * 8;
    const int b_rsel = (lane >> 4);
    const int b_r = (lane & 7);
    const int b_c = ((lane >> 3) & 1) * 8;

    #pragma unroll
    for (int i = 0; i < 16; i++) {
        int pos = tid + i * 128;
        int pl_ = pos >> 10;
        int w   = pos & 1023;
        int row = w >> 3;
        int u   = (w & 7) * 8;
        const __half* src = (pl_ == 0) ? Qhb : Qlb;
        __half* dst = (pl_ == 0) ? qh : ql;
        *(uint4*)&dst[row * AKP + u] = *(const uint4*)(src + (size_t)(q0 + row) * DIM + u);
    }

    auto load_kv = [&](int st, int kvt) {
        const int kv0 = kvt * 64;
        __half* kvbase = smh + OKV0 + st * KVSTG;
        #pragma unroll
        for (int i = 0; i < 16; i++) {
            int uidx = tid + i * 128;
            int p    = uidx >> 9;
            int w    = uidx & 511;
            int row  = w >> 3;
            int u    = (w & 7) * 8;
            const __half* src;
            if (p == 0)      src = Khb;
            else if (p == 1) src = Klb;
            else if (p == 2) src = Vhb;
            else             src = Vlb;
            cp16h(&kvbase[p * 64 * AKP + row * AKP + u],
                  src + (size_t)(kv0 + row) * DIM + u);
        }
    };

    float o[2][8][4];
    float m[4], l[4];
    #pragma unroll
    for (int im = 0; im < 2; im++)
        #pragma unroll
        for (int n = 0; n < 8; n++)
            #pragma unroll
            for (int e = 0; e < 4; e++)
                o[im][n][e] = 0.0f;
    #pragma unroll
    for (int i = 0; i < 4; i++) { m[i] = -INFINITY; l[i] = 0.0f; }

    const int rb  = wid * 32;
    const int wq0 = q0 + rb;
    const int ntiles = 2 * qt + 2;

    load_kv(0, 0);
    cp_commit();
    __syncthreads();

    for (int kvt = 0; kvt < ntiles; kvt++) {
        const int st = kvt & 1;
        const int kv0 = kvt * 64;
        cp_wait<0>();
        __syncthreads();
        if (kvt + 1 < ntiles) { load_kv(st ^ 1, kvt + 1); cp_commit(); }

        const uint32_t kvb = sb + (uint32_t)(OKV0 + st * KVSTG) * 2u;
        const uint32_t khB = kvb;
        const uint32_t klB = kvb + (uint32_t)(64 * AKP) * 2u;
        const uint32_t vhB = kvb + (uint32_t)(2 * 64 * AKP) * 2u;
        const uint32_t vlB = kvb + (uint32_t)(3 * 64 * AKP) * 2u;

        const bool active = (kv0 <= wq0 + 31);
        if (active) {
            float s[2][8][4];
            #pragma unroll
            for (int im = 0; im < 2; im++)
                #pragma unroll
                for (int n = 0; n < 8; n++)
                    #pragma unroll
                    for (int e = 0; e < 4; e++)
                        s[im][n][e] = 0.0f;

            #pragma unroll
            for (int ks = 0; ks < 4; ks++) {
                const int kk = ks * 16;
                uint32_t ahi[2][4], alo[2][4];
                #pragma unroll
                for (int im = 0; im < 2; im++) {
                    uint32_t aoff = (uint32_t)((rb + im * 16 + a_r) * AKP + kk + a_c) * 2u;
                    ldmx4(ahi[im][0], ahi[im][1], ahi[im][2], ahi[im][3],
                          sb + (uint32_t)(OQH * 2) + aoff);
                    ldmx4(alo[im][0], alo[im][1], alo[im][2], alo[im][3],
                          sb + (uint32_t)(OQL * 2) + aoff);
                }
                uint32_t bh[8][2], bl[8][2];
                #pragma unroll
                for (int q = 0; q < 4; q++) {
                    uint32_t boff = (uint32_t)(((2 * q + b_rsel) * 8 + b_r) * AKP
                                               + kk + b_c) * 2u;
                    ldmx4(bh[2*q][0], bh[2*q][1], bh[2*q+1][0], bh[2*q+1][1], khB + boff);
                    ldmx4(bl[2*q][0], bl[2*q][1], bl[2*q+1][0], bl[2*q+1][1], klB + boff);
                }
                #pragma unroll
                for (int im = 0; im < 2; im++)
                    #pragma unroll
                    for (int n = 0; n < 8; n++) {
                        mma16(s[im][n], ahi[im], bh[n]);
                        mma16(s[im][n], ahi[im], bl[n]);
                        mma16(s[im][n], alo[im], bh[n]);
                    }
            }

            const bool needmask = (kv0 + 63) > wq0;
            #pragma unroll
            for (int im = 0; im < 2; im++)
                #pragma unroll
                for (int n = 0; n < 8; n++)
                    #pragma unroll
                    for (int e = 0; e < 4; e++) {
                        float v = s[im][n][e] * 0.125f;
                        if (needmask) {
                            int col = kv0 + n * 8 + 2 * t + (e & 1);
                            int row = wq0 + im * 16 + g + ((e >> 1) * 8);
                            if (col > row) v = -1e30f;
                        }
                        s[im][n][e] = v;
                    }

            #pragma unroll
            for (int im = 0; im < 2; im++) {
                #pragma unroll
                for (int hh = 0; hh < 2; hh++) {
                    int ri = im * 2 + hh;
                    float rowmax = -INFINITY;
                    #pragma unroll
                    for (int n = 0; n < 8; n++) {
                        rowmax = fmaxf(rowmax, s[im][n][hh * 2 + 0]);
                        rowmax = fmaxf(rowmax, s[im][n][hh * 2 + 1]);
                    }
                    rowmax = fmaxf(rowmax, __shfl_xor_sync(0xffffffffu, rowmax, 1));
                    rowmax = fmaxf(rowmax, __shfl_xor_sync(0xffffffffu, rowmax, 2));
                    float mnew = fmaxf(m[ri], rowmax);
                    float alpha = __expf(m[ri] - mnew);
                    m[ri] = mnew;
                    float rs = 0.0f;
                    #pragma unroll
                    for (int n = 0; n < 8; n++) {
                        float p0 = __expf(s[im][n][hh * 2 + 0] - mnew);
                        float p1 = __expf(s[im][n][hh * 2 + 1] - mnew);
                        s[im][n][hh * 2 + 0] = p0;
                        s[im][n][hh * 2 + 1] = p1;
                        rs += p0 + p1;
                    }
                    rs += __shfl_xor_sync(0xffffffffu, rs, 1);
                    rs += __shfl_xor_sync(0xffffffffu, rs, 2);
                    l[ri] = l[ri] * alpha + rs;
                    #pragma unroll
                    for (int n = 0; n < 8; n++) {
                        o[im][n][hh * 2 + 0] *= alpha;
                        o[im][n][hh * 2 + 1] *= alpha;
                    }
                }
            }

            const int rml = ((lane >> 3) & 1) * 8 + (lane & 7);
            const int cml0 = (lane >> 4) * 8;
            #pragma unroll
            for (int ks = 0; ks < 4; ks++) {
                const int kk = ks * 16;
                uint32_t ahi[2][4], alo[2][4];
                #pragma unroll
                for (int im = 0; im < 2; im++) {
                    __half h0, l0_, h1, l1_;
                    splitf(s[im][2*ks][0] * 256.0f, h0, l0_);
                    splitf(s[im][2*ks][1] * 256.0f, h1, l1_);
                    ahi[im][0] = pack2(h0, h1);  alo[im][0] = pack2(l0_, l1_);
                    splitf(s[im][2*ks][2] * 256.0f, h0, l0_);
                    splitf(s[im][2*ks][3] * 256.0f, h1, l1_);
                    ahi[im][1] = pack2(h0, h1);  alo[im][1] = pack2(l0_, l1_);
                    splitf(s[im][2*ks+1][0] * 256.0f, h0, l0_);
                    splitf(s[im][2*ks+1][1] * 256.0f, h1, l1_);
                    ahi[im][2] = pack2(h0, h1);  alo[im][2] = pack2(l0_, l1_);
                    splitf(s[im][2*ks+1][2] * 256.0f, h0, l0_);
                    splitf(s[im][2*ks+1][3] * 256.0f, h1, l1_);
                    ahi[im][3] = pack2(h0, h1);  alo[im][3] = pack2(l0_, l1_);
                }
                #pragma unroll
                for (int nb = 0; nb < 4; nb++) {
                    uint32_t voff = (uint32_t)((kk + rml) * AKP + nb * 16 + cml0) * 2u;
                    uint32_t h0, h1, h2, h3, l0_, l1_, l2_, l3_;
                    ldmx4t(h0, h1, h2, h3, vhB + voff);
                    ldmx4t(l0_, l1_, l2_, l3_, vlB + voff);
                    uint32_t bh0[2] = { h0, h1 }, bh1[2] = { h2, h3 };
                    uint32_t bl0[2] = { l0_, l1_ }, bl1[2] = { l2_, l3_ };
                    #pragma unroll
                    for (int im = 0; im < 2; im++) {
                        mma16(o[im][2 * nb + 0], ahi[im], bh0);
                        mma16(o[im][2 * nb + 0], ahi[im], bl0);
                        mma16(o[im][2 * nb + 0], alo[im], bh0);
                        mma16(o[im][2 * nb + 1], ahi[im], bh1);
                        mma16(o[im][2 * nb + 1], ahi[im], bl1);
                        mma16(o[im][2 * nb + 1], alo[im], bh1);
                    }
                }
            }
        }
        __syncthreads();
    }

    __half* Ohb = g_Oh + base;
    __half* Olb = g_Ol + base;
    #pragma unroll
    for (int im = 0; im < 2; im++) {
        int r0 = q0 + rb + im * 16 + g;
        int r1 = r0 + 8;
        float inv0 = 1.0f / (256.0f * l[im * 2 + 0]);
        float inv1 = 1.0f / (256.0f * l[im * 2 + 1]);
        #pragma unroll
        for (int n = 0; n < 8; n++) {
            int c = n * 8 + 2 * t;
            __half h0, l0_, h1, l1_;
            splitf(o[im][n][0] * inv0, h0, l0_);
            splitf(o[im][n][1] * inv0, h1, l1_);
            *(__half2*)&Ohb[(size_t)r0 * DIM + c] = __halves2half2(h0, h1);
            *(__half2*)&Olb[(size_t)r0 * DIM + c] = __halves2half2(l0_, l1_);
            splitf(o[im][n][2] * inv1, h0, l0_);
            splitf(o[im][n][3] * inv1, h1, l1_);
            *(__half2*)&Ohb[(size_t)r1 * DIM + c] = __halves2half2(h0, h1);
            *(__half2*)&Olb[(size_t)r1 * DIM + c] = __halves2half2(l0_, l1_);
        }
    }
}

// ---------------- launch ----------------
extern "C" void kernel_launch(void* const* d_in, const int* in_sizes, int n_in,
                              void* d_out, int out_size)
{
    const float* x  = (const float*)d_in[0];
    const float* WQ = (const float*)d_in[1];
    const float* WK = (const float*)d_in[2];
    const float* WV = (const float*)d_in[3];
    const float* WO = (const float*)d_in[4];
    const int*  pos = (const int*)d_in[5];
    float* out = (float*)d_out;

    cudaFuncSetAttribute(gemm_h2<true>,  cudaFuncAttributeMaxDynamicSharedMemorySize, GEMM_SMEM);
    cudaFuncSetAttribute(gemm_h2<false>, cudaFuncAttributeMaxDynamicSharedMemorySize, GEMM_SMEM);
    cudaFuncSetAttribute(attn_h2_kernel, cudaFuncAttributeMaxDynamicSharedMemorySize, ATT_SMEM);

    rope_table_kernel<<<(SEQ * 32 + 255) / 256, 256>>>(pos);
    convert_x_kernel<<<(NROWS * DIM / 4 + 255) / 256, 256>>>(x);
    convert_w_all_kernel<<<dim3((DIM * DIM / 4 + 255) / 256, 4), 256>>>(WQ, WK, WV, WO);

    // fused QKV projections: grid.z = mode
    gemm_h2<true><<<dim3(DIM / 128, NROWS / 128, 3), 128, GEMM_SMEM>>>(nullptr);

    attn_h2_kernel<<<dim3(SEQ / 128, BATCH * NHEAD), 128, ATT_SMEM>>>();

    gemm_h2<false><<<dim3(DIM / 128, NROWS / 128, 1), 128, GEMM_SMEM>>>(out);
}